// round 5
// baseline (speedup 1.0000x reference)
#include <cuda_runtime.h>
#include <cuda_fp16.h>
#include <stdint.h>
#include <math.h>

#define D_MODEL 1536
#define S_LEN   4096
#define T_LEN   154
#define N_BC    8
#define N_B     2
#define N_H     24
#define DH      64

// ---------------- scratch (device globals; no allocation allowed) ----------------
__device__ float  g_Q  [N_BC * S_LEN * D_MODEL];
__device__ float  g_K  [N_BC * T_LEN * D_MODEL];
__device__ float  g_V  [N_BC * T_LEN * D_MODEL];
__device__ __half g_HSh [N_BC * S_LEN * D_MODEL];
__device__ __half g_EHSh[N_BC * T_LEN * D_MODEL];
__device__ __half g_AOh [N_BC * S_LEN * D_MODEL];
__device__ __half g_Wqh[D_MODEL * D_MODEL];
__device__ __half g_Wkh[D_MODEL * D_MODEL];
__device__ __half g_Wvh[D_MODEL * D_MODEL];
__device__ __half g_Woh[D_MODEL * D_MODEL];

// ================= helpers =================
__device__ __forceinline__ uint32_t smem_u32(const void* p) {
    uint32_t a;
    asm("{ .reg .u64 t; cvta.to.shared.u64 t, %1; cvt.u32.u64 %0, t; }" : "=r"(a) : "l"(p));
    return a;
}
__device__ __forceinline__ void ldm_x4(uint32_t* r, uint32_t addr) {
    asm volatile("ldmatrix.sync.aligned.m8n8.x4.shared.b16 {%0,%1,%2,%3}, [%4];"
        : "=r"(r[0]), "=r"(r[1]), "=r"(r[2]), "=r"(r[3]) : "r"(addr));
}
__device__ __forceinline__ void mma16816h(float* d, const uint32_t* a,
                                          uint32_t b0, uint32_t b1) {
    asm volatile(
        "mma.sync.aligned.m16n8k16.row.col.f32.f16.f16.f32 "
        "{%0,%1,%2,%3}, {%4,%5,%6,%7}, {%8,%9}, {%0,%1,%2,%3};"
        : "+f"(d[0]), "+f"(d[1]), "+f"(d[2]), "+f"(d[3])
        : "r"(a[0]), "r"(a[1]), "r"(a[2]), "r"(a[3]), "r"(b0), "r"(b1));
}
__device__ __forceinline__ void cp_async16(uint32_t dst, const void* src) {
    asm volatile("cp.async.cg.shared.global [%0], [%1], 16;" :: "r"(dst), "l"(src));
}
#define CP_COMMIT() asm volatile("cp.async.commit_group;" ::: "memory")
#define CP_WAIT(n)  asm volatile("cp.async.wait_group %0;" :: "n"(n) : "memory")

// ================= fp32 -> fp16 convert =================
__global__ void f2h_kernel(const float* __restrict__ x, __half* __restrict__ y, int n4)
{
    int i = blockIdx.x * blockDim.x + threadIdx.x;
    if (i < n4) {
        float4 v = ((const float4*)x)[i];
        __half2* yp = (__half2*)y + i * 2;
        yp[0] = __floats2half2_rn(v.x, v.y);
        yp[1] = __floats2half2_rn(v.z, v.w);
    }
}

// ================= fp16 HGEMM: Y[M,N] = A[M,K] @ B[N,K]^T + bias ====================
// CTA 128x128, BK=32, 128 threads (4 warps 2x2), warp tile 64x64, 3-stage cp.async.
#define LDA    40
#define ASTG   (128 * LDA)
#define STG2   (2 * ASTG)
#define NSTAGE 3
#define GEMM_SMEM_BYTES (NSTAGE * STG2 * 2)   // 61440

__global__ __launch_bounds__(128, 2)
void hgemm_bias(const __half* __restrict__ A, const __half* __restrict__ B,
                const float* __restrict__ bias, float* __restrict__ Y,
                int M, int N, int K)
{
    extern __shared__ __half sm[];
    const uint32_t sbase = smem_u32(sm);
    const int tid  = threadIdx.x;
    const int wid  = tid >> 5;
    const int lane = tid & 31;
    const int bm   = blockIdx.y * 128;
    const int bn   = blockIdx.x * 128;
    const int wm   = wid & 1;          // 64-row half
    const int wn   = wid >> 1;         // 64-col half
    const int xrow = lane & 15;
    const int xk   = (lane >> 4) << 3;

    // loader: 128 threads, each 4 A-chunks + 4 B-chunks of 16B per stage
    const int crow = tid >> 2;              // 0..31
    const int ccol = (tid & 3) << 3;        // 0,8,16,24
    const __half* aptr[4];
    const __half* bptr[4];
    uint32_t soff[4];
    #pragma unroll
    for (int t = 0; t < 4; ++t) {
        int row = crow + t * 32;
        aptr[t] = A + (size_t)min(bm + row, M - 1) * K + ccol;
        bptr[t] = B + (size_t)(bn + row) * K + ccol;
        soff[t] = (uint32_t)(row * LDA + ccol) * 2;
    }

    float acc[4][8][4];
    #pragma unroll
    for (int i = 0; i < 4; ++i)
        #pragma unroll
        for (int j = 0; j < 8; ++j)
            #pragma unroll
            for (int q = 0; q < 4; ++q) acc[i][j][q] = 0.f;

    const int NIT = K / 32;

    auto issue = [&](int it) {
        const int s  = it % NSTAGE;
        const int k0 = it * 32;
        uint32_t sa = sbase + (uint32_t)s * STG2 * 2;
        uint32_t sb = sa + ASTG * 2;
        #pragma unroll
        for (int t = 0; t < 4; ++t) {
            cp_async16(sa + soff[t], aptr[t] + k0);
            cp_async16(sb + soff[t], bptr[t] + k0);
        }
    };

    issue(0); CP_COMMIT();
    issue(1); CP_COMMIT();

    for (int it = 0; it < NIT; ++it) {
        if (it == NIT - 1) { CP_WAIT(0); } else { CP_WAIT(1); }
        __syncthreads();
        if (it + 2 < NIT) { issue(it + 2); CP_COMMIT(); }

        const int s = it % NSTAGE;
        const uint32_t sa = sbase + (uint32_t)s * STG2 * 2;
        const uint32_t sb = sa + ASTG * 2;

        #pragma unroll
        for (int kk = 0; kk < 2; ++kk) {
            const int k0 = kk * 16;
            uint32_t af[4][4];
            #pragma unroll
            for (int mf = 0; mf < 4; ++mf)
                ldm_x4(af[mf], sa + (uint32_t)((wm * 64 + mf * 16 + xrow) * LDA + k0 + xk) * 2);
            #pragma unroll
            for (int nf4 = 0; nf4 < 4; ++nf4) {
                uint32_t bf[4];
                ldm_x4(bf, sb + (uint32_t)((wn * 64 + nf4 * 16 + xrow) * LDA + k0 + xk) * 2);
                #pragma unroll
                for (int mf = 0; mf < 4; ++mf) {
                    mma16816h(acc[mf][nf4 * 2],     af[mf], bf[0], bf[2]);
                    mma16816h(acc[mf][nf4 * 2 + 1], af[mf], bf[1], bf[3]);
                }
            }
        }
    }
    __syncthreads();

    // ---- epilogue: warp covers 64x64 ----
    const int g  = lane >> 2;
    const int t2 = (lane & 3) << 1;
    #pragma unroll
    for (int mf = 0; mf < 4; ++mf) {
        int r0 = bm + wm * 64 + mf * 16 + g;
        #pragma unroll
        for (int nf = 0; nf < 8; ++nf) {
            int col = bn + wn * 64 + nf * 8 + t2;
            float bv0 = bias[col], bv1 = bias[col + 1];
            if (r0 < M) {
                float2 v = make_float2(acc[mf][nf][0] + bv0, acc[mf][nf][1] + bv1);
                *(float2*)(Y + (size_t)r0 * N + col) = v;
            }
            if (r0 + 8 < M) {
                float2 v = make_float2(acc[mf][nf][2] + bv0, acc[mf][nf][3] + bv1);
                *(float2*)(Y + (size_t)(r0 + 8) * N + col) = v;
            }
        }
    }
}

// ---------------- fused decomposing attention (fp32 core, fp16 output) ----------------
#define QTS 36
#define KTS 68
#define SCS 36
#define ATTN_SMEM_FLOATS (4*64*QTS + 4*64*KTS + 4*64*SCS + 128)
#define ATTN_SMEM_BYTES  (ATTN_SMEM_FLOATS * 4)

__global__ __launch_bounds__(256)
void attn_kernel(const float* __restrict__ Q, const float* __restrict__ K,
                 const float* __restrict__ V, __half* __restrict__ O)
{
    extern __shared__ float smemf[];
    float* qT = smemf;
    float* kv = qT + 4 * 64 * QTS;
    float* sc = kv + 4 * 64 * KTS;
    float* rs = sc + 4 * 64 * SCS;

    const int tid = threadIdx.x;
    const int b   = blockIdx.z;
    const int h   = blockIdx.y;
    const int s0  = blockIdx.x * 32;

    if (tid < 128) rs[tid] = 0.f;

    #pragma unroll
    for (int it = 0; it < 8; ++it) {
        int i  = tid + it * 256;
        int c  = i >> 9;
        int r  = i & 511;
        int si = r >> 4;
        int k4 = (r & 15) << 2;
        const float* gp = Q + ((size_t)(c * N_B + b) * S_LEN + (s0 + si)) * D_MODEL + h * DH + k4;
        float4 q4 = *(const float4*)gp;
        float* dst = &qT[(c * 64 + k4) * QTS + si];
        dst[0 * QTS] = q4.x * 0.125f;
        dst[1 * QTS] = q4.y * 0.125f;
        dst[2 * QTS] = q4.z * 0.125f;
        dst[3 * QTS] = q4.w * 0.125f;
    }
    __syncthreads();

    const int oc  = tid >> 6;
    const int orr = tid & 63;
    const int osg = (orr >> 3) << 2;
    const int odg = (orr & 7) << 3;

    float acco[4][8];
    #pragma unroll
    for (int i = 0; i < 4; ++i)
        #pragma unroll
        for (int j = 0; j < 8; ++j) acco[i][j] = 0.f;

    for (int t0 = 0; t0 < T_LEN; t0 += 64) {
        const int tcnt = min(64, T_LEN - t0);

        #pragma unroll
        for (int it = 0; it < 16; ++it) {
            int i  = tid + it * 256;
            int c  = i >> 10;
            int r  = i & 1023;
            int tj = r >> 4;
            int k4 = (r & 15) << 2;
            float4 k4v = make_float4(0.f, 0.f, 0.f, 0.f);
            if (tj < tcnt)
                k4v = *(const float4*)(K + ((size_t)(c * N_B + b) * T_LEN + (t0 + tj)) * D_MODEL + h * DH + k4);
            float* dst = &kv[(c * 64 + k4) * KTS + tj];
            dst[0 * KTS] = k4v.x; dst[1 * KTS] = k4v.y;
            dst[2 * KTS] = k4v.z; dst[3 * KTS] = k4v.w;
        }
        __syncthreads();

        {
            float a[4][8];
            #pragma unroll
            for (int i = 0; i < 4; ++i)
                #pragma unroll
                for (int j = 0; j < 8; ++j) a[i][j] = 0.f;

            #pragma unroll 4
            for (int kk = 0; kk < 64; ++kk) {
                float4 q4 = *(const float4*)&qT[(oc * 64 + kk) * QTS + osg];
                const float* kp = &kv[(oc * 64 + kk) * KTS + odg];
                float4 kA = *(const float4*)kp;
                float4 kB = *(const float4*)(kp + 4);
                float qv[4] = {q4.x, q4.y, q4.z, q4.w};
                float kw[8] = {kA.x, kA.y, kA.z, kA.w, kB.x, kB.y, kB.z, kB.w};
                #pragma unroll
                for (int i = 0; i < 4; ++i)
                    #pragma unroll
                    for (int j = 0; j < 8; ++j)
                        a[i][j] = fmaf(qv[i], kw[j], a[i][j]);
            }
            #pragma unroll
            for (int j = 0; j < 8; ++j) {
                float4 o = make_float4(a[0][j], a[1][j], a[2][j], a[3][j]);
                *(float4*)&sc[(oc * 64 + odg + j) * SCS + osg] = o;
            }
        }
        __syncthreads();

        {
            int s   = tid >> 3;
            int tof = tid & 7;
            float l0 = 0.f, l1 = 0.f, l2 = 0.f, l3 = 0.f;
            for (int t = tof; t < tcnt; t += 8) {
                float x0 = sc[(0 * 64 + t) * SCS + s];
                float x1 = sc[(1 * 64 + t) * SCS + s];
                float x2 = sc[(2 * 64 + t) * SCS + s];
                float x3 = sc[(3 * 64 + t) * SCS + s];
                float m  = fmaxf(fmaxf(x0, x1), fmaxf(x2, x3));
                float e0 = __expf(x0 - m), e1 = __expf(x1 - m);
                float e2 = __expf(x2 - m), e3 = __expf(x3 - m);
                float inv = 1.f / (e0 + e1 + e2 + e3);
                e0 *= inv; e1 *= inv; e2 *= inv; e3 *= inv;
                sc[(0 * 64 + t) * SCS + s] = e0;
                sc[(1 * 64 + t) * SCS + s] = e1;
                sc[(2 * 64 + t) * SCS + s] = e2;
                sc[(3 * 64 + t) * SCS + s] = e3;
                l0 += e0; l1 += e1; l2 += e2; l3 += e3;
            }
            atomicAdd(&rs[s * 4 + 0], l0);
            atomicAdd(&rs[s * 4 + 1], l1);
            atomicAdd(&rs[s * 4 + 2], l2);
            atomicAdd(&rs[s * 4 + 3], l3);
        }

        #pragma unroll
        for (int it = 0; it < 16; ++it) {
            int i  = tid + it * 256;
            int c  = i >> 10;
            int r  = i & 1023;
            int tj = r >> 4;
            int d4 = (r & 15) << 2;
            float4 v4 = make_float4(0.f, 0.f, 0.f, 0.f);
            if (tj < tcnt)
                v4 = *(const float4*)(V + ((size_t)(c * N_B + b) * T_LEN + (t0 + tj)) * D_MODEL + h * DH + d4);
            *(float4*)&kv[(c * 64 + tj) * KTS + d4] = v4;
        }
        __syncthreads();

        for (int tj = 0; tj < tcnt; ++tj) {
            float4 w4 = *(const float4*)&sc[(oc * 64 + tj) * SCS + osg];
            const float* vp = &kv[(oc * 64 + tj) * KTS + odg];
            float4 vA = *(const float4*)vp;
            float4 vB = *(const float4*)(vp + 4);
            float wv[4] = {w4.x, w4.y, w4.z, w4.w};
            float vv[8] = {vA.x, vA.y, vA.z, vA.w, vB.x, vB.y, vB.z, vB.w};
            #pragma unroll
            for (int i = 0; i < 4; ++i)
                #pragma unroll
                for (int j = 0; j < 8; ++j)
                    acco[i][j] = fmaf(wv[i], vv[j], acco[i][j]);
        }
        __syncthreads();
    }

    #pragma unroll
    for (int i = 0; i < 4; ++i) {
        int s = osg + i;
        float inv = 1.f / (rs[s * 4 + oc] + 1e-8f);
        __half* gp = O + ((size_t)(oc * N_B + b) * S_LEN + (s0 + s)) * D_MODEL + h * DH + odg;
        __half2 h0 = __floats2half2_rn(acco[i][0] * inv, acco[i][1] * inv);
        __half2 h1 = __floats2half2_rn(acco[i][2] * inv, acco[i][3] * inv);
        __half2 h2 = __floats2half2_rn(acco[i][4] * inv, acco[i][5] * inv);
        __half2 h3 = __floats2half2_rn(acco[i][6] * inv, acco[i][7] * inv);
        uint4 pk;
        pk.x = *(uint32_t*)&h0; pk.y = *(uint32_t*)&h1;
        pk.z = *(uint32_t*)&h2; pk.w = *(uint32_t*)&h3;
        *(uint4*)gp = pk;
    }
}

// ---------------- launch ----------------
extern "C" void kernel_launch(void* const* d_in, const int* in_sizes, int n_in,
                              void* d_out, int out_size)
{
    const float* HS  = (const float*)d_in[0];
    const float* EHS = (const float*)d_in[1];
    const float* Wq  = (const float*)d_in[2];
    const float* bq  = (const float*)d_in[3];
    const float* Wk  = (const float*)d_in[4];
    const float* bk  = (const float*)d_in[5];
    const float* Wv  = (const float*)d_in[6];
    const float* bv  = (const float*)d_in[7];
    const float* Wo  = (const float*)d_in[8];
    const float* bo  = (const float*)d_in[9];
    float* out = (float*)d_out;

    float *pQ, *pK, *pV;
    __half *pHSh, *pEHSh, *pAOh, *pWqh, *pWkh, *pWvh, *pWoh;
    cudaGetSymbolAddress((void**)&pQ,   g_Q);
    cudaGetSymbolAddress((void**)&pK,   g_K);
    cudaGetSymbolAddress((void**)&pV,   g_V);
    cudaGetSymbolAddress((void**)&pHSh, g_HSh);
    cudaGetSymbolAddress((void**)&pEHSh,g_EHSh);
    cudaGetSymbolAddress((void**)&pAOh, g_AOh);
    cudaGetSymbolAddress((void**)&pWqh, g_Wqh);
    cudaGetSymbolAddress((void**)&pWkh, g_Wkh);
    cudaGetSymbolAddress((void**)&pWvh, g_Wvh);
    cudaGetSymbolAddress((void**)&pWoh, g_Woh);

    cudaFuncSetAttribute(hgemm_bias, cudaFuncAttributeMaxDynamicSharedMemorySize,
                         GEMM_SMEM_BYTES);
    cudaFuncSetAttribute(attn_kernel, cudaFuncAttributeMaxDynamicSharedMemorySize,
                         ATTN_SMEM_BYTES);

    const int nHS = N_BC * S_LEN * D_MODEL / 4;
    const int nEH = N_BC * T_LEN * D_MODEL / 4;
    const int nW  = D_MODEL * D_MODEL / 4;
    f2h_kernel<<<(nHS + 255) / 256, 256>>>(HS,  pHSh,  nHS);
    f2h_kernel<<<(nEH + 255) / 256, 256>>>(EHS, pEHSh, nEH);
    f2h_kernel<<<(nW  + 255) / 256, 256>>>(Wq,  pWqh,  nW);
    f2h_kernel<<<(nW  + 255) / 256, 256>>>(Wk,  pWkh,  nW);
    f2h_kernel<<<(nW  + 255) / 256, 256>>>(Wv,  pWvh,  nW);
    f2h_kernel<<<(nW  + 255) / 256, 256>>>(Wo,  pWoh,  nW);

    dim3 gblk(128);
    // projections
    hgemm_bias<<<dim3(12, 256), gblk, GEMM_SMEM_BYTES>>>(pHSh,  pWqh, bq, pQ, N_BC * S_LEN, D_MODEL, D_MODEL);
    hgemm_bias<<<dim3(12, 10),  gblk, GEMM_SMEM_BYTES>>>(pEHSh, pWkh, bk, pK, N_BC * T_LEN, D_MODEL, D_MODEL);
    hgemm_bias<<<dim3(12, 10),  gblk, GEMM_SMEM_BYTES>>>(pEHSh, pWvh, bv, pV, N_BC * T_LEN, D_MODEL, D_MODEL);
    // fused component-softmax attention (fp16 output)
    attn_kernel<<<dim3(S_LEN / 32, N_H, N_B), 256, ATTN_SMEM_BYTES>>>(pQ, pK, pV, pAOh);
    // output projection into d_out
    hgemm_bias<<<dim3(12, 256), gblk, GEMM_SMEM_BYTES>>>(pAOh, pWoh, bo, out, N_BC * S_LEN, D_MODEL, D_MODEL);
}

// round 6
// speedup vs baseline: 1.7393x; 1.7393x over previous
#include <cuda_runtime.h>
#include <cuda_fp16.h>
#include <stdint.h>
#include <math.h>

#define D_MODEL 1536
#define S_LEN   4096
#define T_LEN   154
#define N_BC    8
#define N_B     2
#define N_H     24
#define DH      64

// ---------------- scratch (device globals; no allocation allowed) ----------------
__device__ __half g_HSh [N_BC * S_LEN * D_MODEL];
__device__ __half g_EHSh[N_BC * T_LEN * D_MODEL];
__device__ __half g_Qh  [N_BC * S_LEN * D_MODEL];
__device__ __half g_Kh  [N_BC * T_LEN * D_MODEL];
__device__ __half g_Vh  [N_BC * T_LEN * D_MODEL];
__device__ __half g_AOh [N_BC * S_LEN * D_MODEL];
__device__ __half g_Wqh[D_MODEL * D_MODEL];
__device__ __half g_Wkh[D_MODEL * D_MODEL];
__device__ __half g_Wvh[D_MODEL * D_MODEL];
__device__ __half g_Woh[D_MODEL * D_MODEL];

// ================= helpers =================
__device__ __forceinline__ uint32_t smem_u32(const void* p) {
    uint32_t a;
    asm("{ .reg .u64 t; cvta.to.shared.u64 t, %1; cvt.u32.u64 %0, t; }" : "=r"(a) : "l"(p));
    return a;
}
__device__ __forceinline__ void ldm_x4(uint32_t* r, uint32_t addr) {
    asm volatile("ldmatrix.sync.aligned.m8n8.x4.shared.b16 {%0,%1,%2,%3}, [%4];"
        : "=r"(r[0]), "=r"(r[1]), "=r"(r[2]), "=r"(r[3]) : "r"(addr));
}
__device__ __forceinline__ void ldm_x4_t(uint32_t* r, uint32_t addr) {
    asm volatile("ldmatrix.sync.aligned.m8n8.x4.trans.shared.b16 {%0,%1,%2,%3}, [%4];"
        : "=r"(r[0]), "=r"(r[1]), "=r"(r[2]), "=r"(r[3]) : "r"(addr));
}
__device__ __forceinline__ void mma16816h(float* d, const uint32_t* a,
                                          uint32_t b0, uint32_t b1) {
    asm volatile(
        "mma.sync.aligned.m16n8k16.row.col.f32.f16.f16.f32 "
        "{%0,%1,%2,%3}, {%4,%5,%6,%7}, {%8,%9}, {%0,%1,%2,%3};"
        : "+f"(d[0]), "+f"(d[1]), "+f"(d[2]), "+f"(d[3])
        : "r"(a[0]), "r"(a[1]), "r"(a[2]), "r"(a[3]), "r"(b0), "r"(b1));
}
__device__ __forceinline__ void cp_async16(uint32_t dst, const void* src) {
    asm volatile("cp.async.cg.shared.global [%0], [%1], 16;" :: "r"(dst), "l"(src));
}
#define CP_COMMIT() asm volatile("cp.async.commit_group;" ::: "memory")
#define CP_WAIT(n)  asm volatile("cp.async.wait_group %0;" :: "n"(n) : "memory")

// ================= fp32 -> fp16 convert =================
__global__ void f2h_kernel(const float* __restrict__ x, __half* __restrict__ y, int n4)
{
    int i = blockIdx.x * blockDim.x + threadIdx.x;
    if (i < n4) {
        float4 v = ((const float4*)x)[i];
        __half2* yp = (__half2*)y + i * 2;
        yp[0] = __floats2half2_rn(v.x, v.y);
        yp[1] = __floats2half2_rn(v.z, v.w);
    }
}

// ================= fp16 HGEMM: Y[M,N] = A[M,K] @ B[N,K]^T + bias ====================
// CTA 128x128, BK=32, 256 threads (8 warps 4x2), warp tile 32x64, 3-stage cp.async.
// HOUT selects fp16 vs fp32 output.
#define LDA    40
#define ASTG   (128 * LDA)
#define STG2   (2 * ASTG)
#define NSTAGE 3
#define GEMM_SMEM_BYTES (NSTAGE * STG2 * 2)   // 61440

template<bool HOUT>
__global__ __launch_bounds__(256, 2)
void hgemm_bias(const __half* __restrict__ A, const __half* __restrict__ B,
                const float* __restrict__ bias, void* __restrict__ Yv,
                int M, int N, int K)
{
    extern __shared__ __half sm[];
    const uint32_t sbase = smem_u32(sm);
    const int tid  = threadIdx.x;
    const int wid  = tid >> 5;
    const int lane = tid & 31;
    const int bm   = blockIdx.y * 128;
    const int bn   = blockIdx.x * 128;
    const int wm   = wid & 3;
    const int wn   = wid >> 2;
    const int xrow = lane & 15;
    const int xk   = (lane >> 4) << 3;

    const int crow = tid >> 2;
    const int ccol = (tid & 3) << 3;
    const int ar0 = min(bm + crow,      M - 1);
    const int ar1 = min(bm + crow + 64, M - 1);
    const __half* a0 = A + (size_t)ar0 * K + ccol;
    const __half* a1 = A + (size_t)ar1 * K + ccol;
    const __half* b0 = B + (size_t)(bn + crow) * K + ccol;
    const __half* b1 = B + (size_t)(bn + crow + 64) * K + ccol;
    const uint32_t so0 = (uint32_t)(crow * LDA + ccol) * 2;
    const uint32_t so1 = (uint32_t)((crow + 64) * LDA + ccol) * 2;

    float acc[2][8][4];
    #pragma unroll
    for (int i = 0; i < 2; ++i)
        #pragma unroll
        for (int j = 0; j < 8; ++j)
            #pragma unroll
            for (int q = 0; q < 4; ++q) acc[i][j][q] = 0.f;

    const int NIT = K / 32;

    auto issue = [&](int it) {
        const int s  = it % NSTAGE;
        const int k0 = it * 32;
        uint32_t sa = sbase + (uint32_t)s * STG2 * 2;
        uint32_t sb = sa + ASTG * 2;
        cp_async16(sa + so0, a0 + k0);
        cp_async16(sa + so1, a1 + k0);
        cp_async16(sb + so0, b0 + k0);
        cp_async16(sb + so1, b1 + k0);
    };

    issue(0); CP_COMMIT();
    issue(1); CP_COMMIT();

    for (int it = 0; it < NIT; ++it) {
        if (it == NIT - 1) { CP_WAIT(0); } else { CP_WAIT(1); }
        __syncthreads();
        if (it + 2 < NIT) { issue(it + 2); CP_COMMIT(); }

        const int s = it % NSTAGE;
        const uint32_t sa = sbase + (uint32_t)s * STG2 * 2;
        const uint32_t sb = sa + ASTG * 2;

        #pragma unroll
        for (int kk = 0; kk < 2; ++kk) {
            const int k0 = kk * 16;
            uint32_t af[2][4];
            #pragma unroll
            for (int mf = 0; mf < 2; ++mf)
                ldm_x4(af[mf], sa + (uint32_t)((wm * 32 + mf * 16 + xrow) * LDA + k0 + xk) * 2);
            #pragma unroll
            for (int nf4 = 0; nf4 < 4; ++nf4) {
                uint32_t bf[4];
                ldm_x4(bf, sb + (uint32_t)((wn * 64 + nf4 * 16 + xrow) * LDA + k0 + xk) * 2);
                #pragma unroll
                for (int mf = 0; mf < 2; ++mf) {
                    mma16816h(acc[mf][nf4 * 2],     af[mf], bf[0], bf[2]);
                    mma16816h(acc[mf][nf4 * 2 + 1], af[mf], bf[1], bf[3]);
                }
            }
        }
    }
    __syncthreads();

    const int g  = lane >> 2;
    const int t2 = (lane & 3) << 1;
    #pragma unroll
    for (int mf = 0; mf < 2; ++mf) {
        int r0 = bm + wm * 32 + mf * 16 + g;
        #pragma unroll
        for (int nf = 0; nf < 8; ++nf) {
            int col = bn + wn * 64 + nf * 8 + t2;
            float bv0 = bias[col], bv1 = bias[col + 1];
            float v00 = acc[mf][nf][0] + bv0, v01 = acc[mf][nf][1] + bv1;
            float v10 = acc[mf][nf][2] + bv0, v11 = acc[mf][nf][3] + bv1;
            if (HOUT) {
                __half* Y = (__half*)Yv;
                if (r0 < M)     *(__half2*)(Y + (size_t)r0 * N + col)       = __floats2half2_rn(v00, v01);
                if (r0 + 8 < M) *(__half2*)(Y + (size_t)(r0 + 8) * N + col) = __floats2half2_rn(v10, v11);
            } else {
                float* Y = (float*)Yv;
                if (r0 < M)     *(float2*)(Y + (size_t)r0 * N + col)       = make_float2(v00, v01);
                if (r0 + 8 < M) *(float2*)(Y + (size_t)(r0 + 8) * N + col) = make_float2(v10, v11);
            }
        }
    }
}

// ================= HMMA decomposing attention ==================================
// Block = (s-tile 32, head, batch), 256 threads (8 warps), all 4 components.
// Per warp: c = wid>>1, half32 = (wid&1)*32 (t-half for scores / d-half for AV).
#define QST 72
#define KST 72
#define VST 72
#define WST 72
#define SCT 68
// smem bytes: qb 18432 + kb 36864 + vb 36864 + wb 18432 + sc 34816 + rs 512
#define ATTN_SMEM_BYTES 145920

__global__ __launch_bounds__(256, 1)
void attn_mma(const __half* __restrict__ Q, const __half* __restrict__ K,
              const __half* __restrict__ V, __half* __restrict__ O)
{
    extern __shared__ char smemc[];
    __half* qb = (__half*)smemc;           // [4][32][QST]
    __half* kb = qb + 4 * 32 * QST;        // [4][64][KST]
    __half* vb = kb + 4 * 64 * KST;        // [4][64][VST]
    __half* wb = vb + 4 * 64 * VST;        // [4][32][WST]
    float*  sc = (float*)(wb + 4 * 32 * WST);   // [4][32][SCT]
    float*  rs = sc + 4 * 32 * SCT;        // [32][4]
    const uint32_t qbu = smem_u32(qb);
    const uint32_t kbu = smem_u32(kb);
    const uint32_t vbu = smem_u32(vb);
    const uint32_t wbu = smem_u32(wb);

    const int tid  = threadIdx.x;
    const int wid  = tid >> 5;
    const int lane = tid & 31;
    const int b    = blockIdx.z;
    const int h    = blockIdx.y;
    const int s0   = blockIdx.x * 32;

    const int c      = wid >> 1;
    const int half32 = (wid & 1) * 32;
    const int xrow   = lane & 15;
    const int xk     = (lane >> 4) << 3;
    const int g      = lane >> 2;
    const int t2     = (lane & 3) << 1;

    if (tid < 128) rs[tid] = 0.f;

    // ---- load Q tile (fp16, natural layout) ----
    #pragma unroll
    for (int it = 0; it < 4; ++it) {
        int i  = tid + it * 256;
        int cc = i >> 8, r = i & 255, si = r >> 3, d8 = (r & 7) << 3;
        const __half* gp = Q + ((size_t)(cc * N_B + b) * S_LEN + s0 + si) * D_MODEL + h * DH + d8;
        *(uint4*)(qb + (cc * 32 + si) * QST + d8) = *(const uint4*)gp;
    }
    __syncthreads();

    float oacc[2][4][4];
    #pragma unroll
    for (int i = 0; i < 2; ++i)
        #pragma unroll
        for (int j = 0; j < 4; ++j)
            #pragma unroll
            for (int q = 0; q < 4; ++q) oacc[i][j][q] = 0.f;

    for (int t0 = 0; t0 < T_LEN; t0 += 64) {
        const int tcnt = min(64, T_LEN - t0);

        // ---- load K,V tiles (zero-fill padding) ----
        #pragma unroll
        for (int it = 0; it < 8; ++it) {
            int i  = tid + it * 256;
            int cc = i >> 9, r = i & 511, tj = r >> 3, d8 = (r & 7) << 3;
            uint4 kz = make_uint4(0, 0, 0, 0), vz = make_uint4(0, 0, 0, 0);
            if (tj < tcnt) {
                size_t go = ((size_t)(cc * N_B + b) * T_LEN + t0 + tj) * D_MODEL + h * DH + d8;
                kz = *(const uint4*)(K + go);
                vz = *(const uint4*)(V + go);
            }
            *(uint4*)(kb + (cc * 64 + tj) * KST + d8) = kz;
            *(uint4*)(vb + (cc * 64 + tj) * VST + d8) = vz;
        }
        __syncthreads();

        // ---- scores: warp computes S[c][s 0..31][t half32..+31] ----
        {
            float sa[2][4][4];
            #pragma unroll
            for (int i = 0; i < 2; ++i)
                #pragma unroll
                for (int j = 0; j < 4; ++j)
                    #pragma unroll
                    for (int q = 0; q < 4; ++q) sa[i][j][q] = 0.f;

            #pragma unroll
            for (int kk = 0; kk < 4; ++kk) {
                const int k0 = kk * 16 + xk;
                uint32_t af[2][4];
                #pragma unroll
                for (int mf = 0; mf < 2; ++mf)
                    ldm_x4(af[mf], qbu + (uint32_t)((c * 32 + mf * 16 + xrow) * QST + k0) * 2);
                #pragma unroll
                for (int nf16 = 0; nf16 < 2; ++nf16) {
                    uint32_t bf[4];
                    ldm_x4(bf, kbu + (uint32_t)((c * 64 + half32 + nf16 * 16 + xrow) * KST + k0) * 2);
                    #pragma unroll
                    for (int mf = 0; mf < 2; ++mf) {
                        mma16816h(sa[mf][nf16 * 2],     af[mf], bf[0], bf[2]);
                        mma16816h(sa[mf][nf16 * 2 + 1], af[mf], bf[1], bf[3]);
                    }
                }
            }
            // store scores * dh^-0.5
            #pragma unroll
            for (int mf = 0; mf < 2; ++mf)
                #pragma unroll
                for (int nf8 = 0; nf8 < 4; ++nf8) {
                    int col = half32 + nf8 * 8 + t2;
                    float* p0 = sc + (c * 32 + mf * 16 + g) * SCT + col;
                    *(float2*)p0             = make_float2(sa[mf][nf8][0] * 0.125f, sa[mf][nf8][1] * 0.125f);
                    *(float2*)(p0 + 8 * SCT) = make_float2(sa[mf][nf8][2] * 0.125f, sa[mf][nf8][3] * 0.125f);
                }
        }
        __syncthreads();

        // ---- softmax over components + key-sum + fp16 weight emit ----
        {
            int s = tid >> 3, toff = tid & 7;
            float l0 = 0.f, l1 = 0.f, l2 = 0.f, l3 = 0.f;
            #pragma unroll
            for (int t = toff; t < 64; t += 8) {
                float x0 = sc[(0 * 32 + s) * SCT + t];
                float x1 = sc[(1 * 32 + s) * SCT + t];
                float x2 = sc[(2 * 32 + s) * SCT + t];
                float x3 = sc[(3 * 32 + s) * SCT + t];
                float m  = fmaxf(fmaxf(x0, x1), fmaxf(x2, x3));
                float e0 = __expf(x0 - m), e1 = __expf(x1 - m);
                float e2 = __expf(x2 - m), e3 = __expf(x3 - m);
                float inv = (t < tcnt) ? (1.f / (e0 + e1 + e2 + e3)) : 0.f;
                e0 *= inv; e1 *= inv; e2 *= inv; e3 *= inv;
                wb[(0 * 32 + s) * WST + t] = __float2half_rn(e0);
                wb[(1 * 32 + s) * WST + t] = __float2half_rn(e1);
                wb[(2 * 32 + s) * WST + t] = __float2half_rn(e2);
                wb[(3 * 32 + s) * WST + t] = __float2half_rn(e3);
                l0 += e0; l1 += e1; l2 += e2; l3 += e3;
            }
            atomicAdd(&rs[s * 4 + 0], l0);
            atomicAdd(&rs[s * 4 + 1], l1);
            atomicAdd(&rs[s * 4 + 2], l2);
            atomicAdd(&rs[s * 4 + 3], l3);
        }
        __syncthreads();

        // ---- AV: oacc[c][s 0..31][d half32..+31] += W @ V ----
        #pragma unroll
        for (int kk = 0; kk < 4; ++kk) {
            const int k0 = kk * 16;
            uint32_t af[2][4];
            #pragma unroll
            for (int mf = 0; mf < 2; ++mf)
                ldm_x4(af[mf], wbu + (uint32_t)((c * 32 + mf * 16 + xrow) * WST + k0 + xk) * 2);
            #pragma unroll
            for (int nf16 = 0; nf16 < 2; ++nf16) {
                uint32_t bf[4];
                ldm_x4_t(bf, vbu + (uint32_t)((c * 64 + k0 + xrow) * VST + half32 + nf16 * 16 + xk) * 2);
                #pragma unroll
                for (int mf = 0; mf < 2; ++mf) {
                    mma16816h(oacc[mf][nf16 * 2],     af[mf], bf[0], bf[1]);
                    mma16816h(oacc[mf][nf16 * 2 + 1], af[mf], bf[2], bf[3]);
                }
            }
        }
        __syncthreads();
    }

    // ---- renormalize by key-sum and store fp16 ----
    #pragma unroll
    for (int mf = 0; mf < 2; ++mf) {
        #pragma unroll
        for (int rr = 0; rr < 2; ++rr) {
            int row = mf * 16 + rr * 8 + g;
            float inv = 1.f / (rs[row * 4 + c] + 1e-8f);
            __half* gp = O + ((size_t)(c * N_B + b) * S_LEN + s0 + row) * D_MODEL + h * DH;
            #pragma unroll
            for (int nf8 = 0; nf8 < 4; ++nf8) {
                int d = half32 + nf8 * 8 + t2;
                float v0 = oacc[mf][nf8][rr * 2 + 0] * inv;
                float v1 = oacc[mf][nf8][rr * 2 + 1] * inv;
                *(__half2*)(gp + d) = __floats2half2_rn(v0, v1);
            }
        }
    }
}

// ---------------- launch ----------------
extern "C" void kernel_launch(void* const* d_in, const int* in_sizes, int n_in,
                              void* d_out, int out_size)
{
    const float* HS  = (const float*)d_in[0];
    const float* EHS = (const float*)d_in[1];
    const float* Wq  = (const float*)d_in[2];
    const float* bq  = (const float*)d_in[3];
    const float* Wk  = (const float*)d_in[4];
    const float* bk  = (const float*)d_in[5];
    const float* Wv  = (const float*)d_in[6];
    const float* bv  = (const float*)d_in[7];
    const float* Wo  = (const float*)d_in[8];
    const float* bo  = (const float*)d_in[9];
    float* out = (float*)d_out;

    __half *pHSh, *pEHSh, *pQh, *pKh, *pVh, *pAOh, *pWqh, *pWkh, *pWvh, *pWoh;
    cudaGetSymbolAddress((void**)&pHSh,  g_HSh);
    cudaGetSymbolAddress((void**)&pEHSh, g_EHSh);
    cudaGetSymbolAddress((void**)&pQh,   g_Qh);
    cudaGetSymbolAddress((void**)&pKh,   g_Kh);
    cudaGetSymbolAddress((void**)&pVh,   g_Vh);
    cudaGetSymbolAddress((void**)&pAOh,  g_AOh);
    cudaGetSymbolAddress((void**)&pWqh,  g_Wqh);
    cudaGetSymbolAddress((void**)&pWkh,  g_Wkh);
    cudaGetSymbolAddress((void**)&pWvh,  g_Wvh);
    cudaGetSymbolAddress((void**)&pWoh,  g_Woh);

    cudaFuncSetAttribute(hgemm_bias<true>,  cudaFuncAttributeMaxDynamicSharedMemorySize, GEMM_SMEM_BYTES);
    cudaFuncSetAttribute(hgemm_bias<false>, cudaFuncAttributeMaxDynamicSharedMemorySize, GEMM_SMEM_BYTES);
    cudaFuncSetAttribute(attn_mma, cudaFuncAttributeMaxDynamicSharedMemorySize, ATTN_SMEM_BYTES);

    const int nHS = N_BC * S_LEN * D_MODEL / 4;
    const int nEH = N_BC * T_LEN * D_MODEL / 4;
    const int nW  = D_MODEL * D_MODEL / 4;
    f2h_kernel<<<(nHS + 255) / 256, 256>>>(HS,  pHSh,  nHS);
    f2h_kernel<<<(nEH + 255) / 256, 256>>>(EHS, pEHSh, nEH);
    f2h_kernel<<<(nW  + 255) / 256, 256>>>(Wq,  pWqh,  nW);
    f2h_kernel<<<(nW  + 255) / 256, 256>>>(Wk,  pWkh,  nW);
    f2h_kernel<<<(nW  + 255) / 256, 256>>>(Wv,  pWvh,  nW);
    f2h_kernel<<<(nW  + 255) / 256, 256>>>(Wo,  pWoh,  nW);

    dim3 gblk(256);
    // projections (fp16 outputs)
    hgemm_bias<true><<<dim3(12, 256), gblk, GEMM_SMEM_BYTES>>>(pHSh,  pWqh, bq, pQh, N_BC * S_LEN, D_MODEL, D_MODEL);
    hgemm_bias<true><<<dim3(12, 10),  gblk, GEMM_SMEM_BYTES>>>(pEHSh, pWkh, bk, pKh, N_BC * T_LEN, D_MODEL, D_MODEL);
    hgemm_bias<true><<<dim3(12, 10),  gblk, GEMM_SMEM_BYTES>>>(pEHSh, pWvh, bv, pVh, N_BC * T_LEN, D_MODEL, D_MODEL);
    // HMMA decomposing attention (fp16 in/out)
    attn_mma<<<dim3(S_LEN / 32, N_H, N_B), 256, ATTN_SMEM_BYTES>>>(pQh, pKh, pVh, pAOh);
    // output projection (fp32 output into d_out)
    hgemm_bias<false><<<dim3(12, 256), gblk, GEMM_SMEM_BYTES>>>(pAOh, pWoh, bo, out, N_BC * S_LEN, D_MODEL, D_MODEL);
}

// round 7
// speedup vs baseline: 1.9531x; 1.1229x over previous
#include <cuda_runtime.h>
#include <cuda_fp16.h>
#include <stdint.h>
#include <math.h>

#define D_MODEL 1536
#define S_LEN   4096
#define T_LEN   154
#define N_BC    8
#define N_B     2
#define N_H     24
#define DH      64

// ---------------- scratch (device globals; no allocation allowed) ----------------
__device__ __half g_HSh [N_BC * S_LEN * D_MODEL];
__device__ __half g_EHSh[N_BC * T_LEN * D_MODEL];
__device__ __half g_Qh  [N_BC * S_LEN * D_MODEL];
__device__ __half g_Kh  [N_BC * T_LEN * D_MODEL];
__device__ __half g_Vh  [N_BC * T_LEN * D_MODEL];
__device__ __half g_AOh [N_BC * S_LEN * D_MODEL];
__device__ __half g_Wqh[D_MODEL * D_MODEL];
__device__ __half g_Wkh[D_MODEL * D_MODEL];
__device__ __half g_Wvh[D_MODEL * D_MODEL];
__device__ __half g_Woh[D_MODEL * D_MODEL];

// ================= helpers =================
__device__ __forceinline__ uint32_t smem_u32(const void* p) {
    uint32_t a;
    asm("{ .reg .u64 t; cvta.to.shared.u64 t, %1; cvt.u32.u64 %0, t; }" : "=r"(a) : "l"(p));
    return a;
}
__device__ __forceinline__ void ldm_x4(uint32_t* r, uint32_t addr) {
    asm volatile("ldmatrix.sync.aligned.m8n8.x4.shared.b16 {%0,%1,%2,%3}, [%4];"
        : "=r"(r[0]), "=r"(r[1]), "=r"(r[2]), "=r"(r[3]) : "r"(addr));
}
__device__ __forceinline__ void ldm_x4_t(uint32_t* r, uint32_t addr) {
    asm volatile("ldmatrix.sync.aligned.m8n8.x4.trans.shared.b16 {%0,%1,%2,%3}, [%4];"
        : "=r"(r[0]), "=r"(r[1]), "=r"(r[2]), "=r"(r[3]) : "r"(addr));
}
__device__ __forceinline__ void mma16816h(float* d, const uint32_t* a,
                                          uint32_t b0, uint32_t b1) {
    asm volatile(
        "mma.sync.aligned.m16n8k16.row.col.f32.f16.f16.f32 "
        "{%0,%1,%2,%3}, {%4,%5,%6,%7}, {%8,%9}, {%0,%1,%2,%3};"
        : "+f"(d[0]), "+f"(d[1]), "+f"(d[2]), "+f"(d[3])
        : "r"(a[0]), "r"(a[1]), "r"(a[2]), "r"(a[3]), "r"(b0), "r"(b1));
}
__device__ __forceinline__ void cp_async16(uint32_t dst, const void* src) {
    asm volatile("cp.async.cg.shared.global [%0], [%1], 16;" :: "r"(dst), "l"(src));
}
#define CP_COMMIT() asm volatile("cp.async.commit_group;" ::: "memory")
#define CP_WAIT(n)  asm volatile("cp.async.wait_group %0;" :: "n"(n) : "memory")

__device__ __forceinline__ uint32_t packh2(float a, float b) {
    __half2 h = __floats2half2_rn(a, b);
    return *(uint32_t*)&h;
}

// ================= fp32 -> fp16 convert =================
__global__ void f2h_kernel(const float* __restrict__ x, __half* __restrict__ y, int n4)
{
    int i = blockIdx.x * blockDim.x + threadIdx.x;
    if (i < n4) {
        float4 v = ((const float4*)x)[i];
        __half2* yp = (__half2*)y + i * 2;
        yp[0] = __floats2half2_rn(v.x, v.y);
        yp[1] = __floats2half2_rn(v.z, v.w);
    }
}

// ================= fp16 HGEMM: Y[M,N] = A[M,K] @ B[N,K]^T + bias ====================
#define LDA    40
#define ASTG   (128 * LDA)
#define STG2   (2 * ASTG)
#define NSTAGE 3
#define GEMM_SMEM_BYTES (NSTAGE * STG2 * 2)   // 61440

template<bool HOUT>
__global__ __launch_bounds__(256, 2)
void hgemm_bias(const __half* __restrict__ A, const __half* __restrict__ B,
                const float* __restrict__ bias, void* __restrict__ Yv,
                int M, int N, int K)
{
    extern __shared__ __half sm[];
    const uint32_t sbase = smem_u32(sm);
    const int tid  = threadIdx.x;
    const int wid  = tid >> 5;
    const int lane = tid & 31;
    const int bm   = blockIdx.y * 128;
    const int bn   = blockIdx.x * 128;
    const int wm   = wid & 3;
    const int wn   = wid >> 2;
    const int xrow = lane & 15;
    const int xk   = (lane >> 4) << 3;

    const int crow = tid >> 2;
    const int ccol = (tid & 3) << 3;
    const int ar0 = min(bm + crow,      M - 1);
    const int ar1 = min(bm + crow + 64, M - 1);
    const __half* a0 = A + (size_t)ar0 * K + ccol;
    const __half* a1 = A + (size_t)ar1 * K + ccol;
    const __half* b0 = B + (size_t)(bn + crow) * K + ccol;
    const __half* b1 = B + (size_t)(bn + crow + 64) * K + ccol;
    const uint32_t so0 = (uint32_t)(crow * LDA + ccol) * 2;
    const uint32_t so1 = (uint32_t)((crow + 64) * LDA + ccol) * 2;

    float acc[2][8][4];
    #pragma unroll
    for (int i = 0; i < 2; ++i)
        #pragma unroll
        for (int j = 0; j < 8; ++j)
            #pragma unroll
            for (int q = 0; q < 4; ++q) acc[i][j][q] = 0.f;

    const int NIT = K / 32;

    auto issue = [&](int it) {
        const int s  = it % NSTAGE;
        const int k0 = it * 32;
        uint32_t sa = sbase + (uint32_t)s * STG2 * 2;
        uint32_t sb = sa + ASTG * 2;
        cp_async16(sa + so0, a0 + k0);
        cp_async16(sa + so1, a1 + k0);
        cp_async16(sb + so0, b0 + k0);
        cp_async16(sb + so1, b1 + k0);
    };

    issue(0); CP_COMMIT();
    issue(1); CP_COMMIT();

    for (int it = 0; it < NIT; ++it) {
        if (it == NIT - 1) { CP_WAIT(0); } else { CP_WAIT(1); }
        __syncthreads();
        if (it + 2 < NIT) { issue(it + 2); CP_COMMIT(); }

        const int s = it % NSTAGE;
        const uint32_t sa = sbase + (uint32_t)s * STG2 * 2;
        const uint32_t sb = sa + ASTG * 2;

        #pragma unroll
        for (int kk = 0; kk < 2; ++kk) {
            const int k0 = kk * 16;
            uint32_t af[2][4];
            #pragma unroll
            for (int mf = 0; mf < 2; ++mf)
                ldm_x4(af[mf], sa + (uint32_t)((wm * 32 + mf * 16 + xrow) * LDA + k0 + xk) * 2);
            #pragma unroll
            for (int nf4 = 0; nf4 < 4; ++nf4) {
                uint32_t bf[4];
                ldm_x4(bf, sb + (uint32_t)((wn * 64 + nf4 * 16 + xrow) * LDA + k0 + xk) * 2);
                #pragma unroll
                for (int mf = 0; mf < 2; ++mf) {
                    mma16816h(acc[mf][nf4 * 2],     af[mf], bf[0], bf[2]);
                    mma16816h(acc[mf][nf4 * 2 + 1], af[mf], bf[1], bf[3]);
                }
            }
        }
    }
    __syncthreads();

    const int g  = lane >> 2;
    const int t2 = (lane & 3) << 1;
    #pragma unroll
    for (int mf = 0; mf < 2; ++mf) {
        int r0 = bm + wm * 32 + mf * 16 + g;
        #pragma unroll
        for (int nf = 0; nf < 8; ++nf) {
            int col = bn + wn * 64 + nf * 8 + t2;
            float bv0 = bias[col], bv1 = bias[col + 1];
            float v00 = acc[mf][nf][0] + bv0, v01 = acc[mf][nf][1] + bv1;
            float v10 = acc[mf][nf][2] + bv0, v11 = acc[mf][nf][3] + bv1;
            if (HOUT) {
                __half* Y = (__half*)Yv;
                if (r0 < M)     *(__half2*)(Y + (size_t)r0 * N + col)       = __floats2half2_rn(v00, v01);
                if (r0 + 8 < M) *(__half2*)(Y + (size_t)(r0 + 8) * N + col) = __floats2half2_rn(v10, v11);
            } else {
                float* Y = (float*)Yv;
                if (r0 < M)     *(float2*)(Y + (size_t)r0 * N + col)       = make_float2(v00, v01);
                if (r0 + 8 < M) *(float2*)(Y + (size_t)(r0 + 8) * N + col) = make_float2(v10, v11);
            }
        }
    }
}

// ================= register-softmax HMMA attention ==============================
// CTA: 128 threads (4 warps), s-tile 32. Warp = (s-sub 16 rows) x (d-half 32).
// Each warp handles ALL 4 components -> softmax over c entirely in registers.
#define QST 72
#define KST 72
#define KV_MAT   (4 * 32 * KST * 2)            // 18432 B (one matrix chunk)
#define KV_STAGE (2 * KV_MAT)                  // 36864 B (K + V)
#define ATTN_SMEM_BYTES (4 * 32 * QST * 2 + 2 * KV_STAGE)   // 92160

__global__ __launch_bounds__(128, 2)
void attn_reg(const __half* __restrict__ Q, const __half* __restrict__ K,
              const __half* __restrict__ V, __half* __restrict__ O)
{
    extern __shared__ char smemc[];
    __half* qb = (__half*)smemc;                 // [4][32][QST]
    const uint32_t qbu = smem_u32(qb);
    const uint32_t kvu = qbu + 4 * 32 * QST * 2;

    const int tid  = threadIdx.x;
    const int wid  = tid >> 5;
    const int lane = tid & 31;
    const int b    = blockIdx.z;
    const int h    = blockIdx.y;
    const int s0   = blockIdx.x * 32;

    const int sbase = (wid >> 1) * 16;   // 0 / 16
    const int dbase = (wid & 1) * 32;    // 0 / 32
    const int xrow  = lane & 15;
    const int xk    = (lane >> 4) << 3;
    const int g     = lane >> 2;
    const int q2    = (lane & 3) << 1;

    // ---- load Q tile: 4c x 32s x 64d = 1024 uint4, 8 per thread ----
    #pragma unroll
    for (int it = 0; it < 8; ++it) {
        int i  = tid + it * 128;
        int cc = i >> 8, r = i & 255, si = r >> 3, d8 = (r & 7) << 3;
        const __half* gp = Q + ((size_t)(cc * N_B + b) * S_LEN + s0 + si) * D_MODEL + h * DH + d8;
        *(uint4*)(qb + (cc * 32 + si) * QST + d8) = *(const uint4*)gp;
    }

    const int NCH = (T_LEN + 31) / 32;   // 5

    auto issue = [&](int ch) {
        const int t0 = ch * 32;
        const uint32_t st = kvu + (uint32_t)(ch & 1) * KV_STAGE;
        #pragma unroll
        for (int it = 0; it < 8; ++it) {
            int i  = tid + it * 128;
            int cc = i >> 8, r = i & 255, tj = r >> 3, d8 = (r & 7) << 3;
            int t = min(t0 + tj, T_LEN - 1);     // clamp; w zeroed for t>=T_LEN
            size_t go = ((size_t)(cc * N_B + b) * T_LEN + t) * D_MODEL + h * DH + d8;
            uint32_t so = (uint32_t)((cc * 32 + tj) * KST + d8) * 2;
            cp_async16(st + so, K + go);
            cp_async16(st + KV_MAT + so, V + go);
        }
    };

    issue(0); CP_COMMIT();
    issue(1); CP_COMMIT();

    float oacc[4][4][4];
    #pragma unroll
    for (int c = 0; c < 4; ++c)
        #pragma unroll
        for (int j = 0; j < 4; ++j)
            #pragma unroll
            for (int e = 0; e < 4; ++e) oacc[c][j][e] = 0.f;
    float rsum[2][4];
    #pragma unroll
    for (int r = 0; r < 2; ++r)
        #pragma unroll
        for (int c = 0; c < 4; ++c) rsum[r][c] = 0.f;

    for (int ch = 0; ch < NCH; ++ch) {
        if (ch == NCH - 1) { CP_WAIT(0); } else { CP_WAIT(1); }
        __syncthreads();

        const uint32_t kbu = kvu + (uint32_t)(ch & 1) * KV_STAGE;
        const uint32_t vbu = kbu + KV_MAT;

        // ---- scores: sacc[c][j n8][e], tile = 16s x 32t ----
        float sacc[4][4][4];
        #pragma unroll
        for (int c = 0; c < 4; ++c)
            #pragma unroll
            for (int j = 0; j < 4; ++j)
                #pragma unroll
                for (int e = 0; e < 4; ++e) sacc[c][j][e] = 0.f;

        #pragma unroll
        for (int c = 0; c < 4; ++c) {
            #pragma unroll
            for (int kk = 0; kk < 4; ++kk) {
                uint32_t af[4];
                ldm_x4(af, qbu + (uint32_t)((c * 32 + sbase + xrow) * QST + kk * 16 + xk) * 2);
                #pragma unroll
                for (int nf16 = 0; nf16 < 2; ++nf16) {
                    uint32_t bf[4];
                    ldm_x4(bf, kbu + (uint32_t)((c * 32 + nf16 * 16 + xrow) * KST + kk * 16 + xk) * 2);
                    mma16816h(sacc[c][nf16 * 2],     af, bf[0], bf[2]);
                    mma16816h(sacc[c][nf16 * 2 + 1], af, bf[1], bf[3]);
                }
            }
        }

        // ---- register softmax over components + repack into A-fragments ----
        uint32_t wfrag[4][2][4];
        #pragma unroll
        for (int j = 0; j < 4; ++j) {
            float wt[4][4];
            #pragma unroll
            for (int e = 0; e < 4; ++e) {
                int col = ch * 32 + j * 8 + q2 + (e & 1);
                float x0 = sacc[0][j][e] * 0.125f;
                float x1 = sacc[1][j][e] * 0.125f;
                float x2 = sacc[2][j][e] * 0.125f;
                float x3 = sacc[3][j][e] * 0.125f;
                float m  = fmaxf(fmaxf(x0, x1), fmaxf(x2, x3));
                float e0 = __expf(x0 - m), e1 = __expf(x1 - m);
                float e2 = __expf(x2 - m), e3 = __expf(x3 - m);
                float inv = (col < T_LEN) ? (1.f / (e0 + e1 + e2 + e3)) : 0.f;
                e0 *= inv; e1 *= inv; e2 *= inv; e3 *= inv;
                int rr = e >> 1;
                rsum[rr][0] += e0; rsum[rr][1] += e1;
                rsum[rr][2] += e2; rsum[rr][3] += e3;
                wt[0][e] = e0; wt[1][e] = e1; wt[2][e] = e2; wt[3][e] = e3;
            }
            #pragma unroll
            for (int c = 0; c < 4; ++c) {
                wfrag[c][j >> 1][(j & 1) * 2 + 0] = packh2(wt[c][0], wt[c][1]);
                wfrag[c][j >> 1][(j & 1) * 2 + 1] = packh2(wt[c][2], wt[c][3]);
            }
        }

        // ---- AV: oacc[c][16s x 32d-half] += W @ V ----
        #pragma unroll
        for (int c = 0; c < 4; ++c) {
            #pragma unroll
            for (int kk = 0; kk < 2; ++kk) {
                #pragma unroll
                for (int nf16 = 0; nf16 < 2; ++nf16) {
                    uint32_t bf[4];
                    ldm_x4_t(bf, vbu + (uint32_t)((c * 32 + kk * 16 + xrow) * KST + dbase + nf16 * 16 + xk) * 2);
                    mma16816h(oacc[c][nf16 * 2],     wfrag[c][kk], bf[0], bf[1]);
                    mma16816h(oacc[c][nf16 * 2 + 1], wfrag[c][kk], bf[2], bf[3]);
                }
            }
        }
        __syncthreads();
        if (ch + 2 < NCH) { issue(ch + 2); CP_COMMIT(); }
    }

    // ---- finalize row sums across quad lanes ----
    #pragma unroll
    for (int x = 1; x <= 2; x <<= 1)
        #pragma unroll
        for (int r = 0; r < 2; ++r)
            #pragma unroll
            for (int c = 0; c < 4; ++c)
                rsum[r][c] += __shfl_xor_sync(0xffffffffu, rsum[r][c], x);

    // ---- renormalize and store ----
    #pragma unroll
    for (int c = 0; c < 4; ++c) {
        float inv0 = 1.f / (rsum[0][c] + 1e-8f);
        float inv1 = 1.f / (rsum[1][c] + 1e-8f);
        int row0 = s0 + sbase + g;
        __half* gp0 = O + ((size_t)(c * N_B + b) * S_LEN + row0) * D_MODEL + h * DH + dbase + q2;
        __half* gp1 = gp0 + (size_t)8 * D_MODEL;
        #pragma unroll
        for (int j = 0; j < 4; ++j) {
            *(__half2*)(gp0 + j * 8) = __floats2half2_rn(oacc[c][j][0] * inv0, oacc[c][j][1] * inv0);
            *(__half2*)(gp1 + j * 8) = __floats2half2_rn(oacc[c][j][2] * inv1, oacc[c][j][3] * inv1);
        }
    }
}

// ---------------- launch ----------------
extern "C" void kernel_launch(void* const* d_in, const int* in_sizes, int n_in,
                              void* d_out, int out_size)
{
    const float* HS  = (const float*)d_in[0];
    const float* EHS = (const float*)d_in[1];
    const float* Wq  = (const float*)d_in[2];
    const float* bq  = (const float*)d_in[3];
    const float* Wk  = (const float*)d_in[4];
    const float* bk  = (const float*)d_in[5];
    const float* Wv  = (const float*)d_in[6];
    const float* bv  = (const float*)d_in[7];
    const float* Wo  = (const float*)d_in[8];
    const float* bo  = (const float*)d_in[9];
    float* out = (float*)d_out;

    __half *pHSh, *pEHSh, *pQh, *pKh, *pVh, *pAOh, *pWqh, *pWkh, *pWvh, *pWoh;
    cudaGetSymbolAddress((void**)&pHSh,  g_HSh);
    cudaGetSymbolAddress((void**)&pEHSh, g_EHSh);
    cudaGetSymbolAddress((void**)&pQh,   g_Qh);
    cudaGetSymbolAddress((void**)&pKh,   g_Kh);
    cudaGetSymbolAddress((void**)&pVh,   g_Vh);
    cudaGetSymbolAddress((void**)&pAOh,  g_AOh);
    cudaGetSymbolAddress((void**)&pWqh,  g_Wqh);
    cudaGetSymbolAddress((void**)&pWkh,  g_Wkh);
    cudaGetSymbolAddress((void**)&pWvh,  g_Wvh);
    cudaGetSymbolAddress((void**)&pWoh,  g_Woh);

    cudaFuncSetAttribute(hgemm_bias<true>,  cudaFuncAttributeMaxDynamicSharedMemorySize, GEMM_SMEM_BYTES);
    cudaFuncSetAttribute(hgemm_bias<false>, cudaFuncAttributeMaxDynamicSharedMemorySize, GEMM_SMEM_BYTES);
    cudaFuncSetAttribute(attn_reg, cudaFuncAttributeMaxDynamicSharedMemorySize, ATTN_SMEM_BYTES);

    const int nHS = N_BC * S_LEN * D_MODEL / 4;
    const int nEH = N_BC * T_LEN * D_MODEL / 4;
    const int nW  = D_MODEL * D_MODEL / 4;
    f2h_kernel<<<(nHS + 255) / 256, 256>>>(HS,  pHSh,  nHS);
    f2h_kernel<<<(nEH + 255) / 256, 256>>>(EHS, pEHSh, nEH);
    f2h_kernel<<<(nW  + 255) / 256, 256>>>(Wq,  pWqh,  nW);
    f2h_kernel<<<(nW  + 255) / 256, 256>>>(Wk,  pWkh,  nW);
    f2h_kernel<<<(nW  + 255) / 256, 256>>>(Wv,  pWvh,  nW);
    f2h_kernel<<<(nW  + 255) / 256, 256>>>(Wo,  pWoh,  nW);

    dim3 gblk(256);
    // projections (fp16 outputs)
    hgemm_bias<true><<<dim3(12, 256), gblk, GEMM_SMEM_BYTES>>>(pHSh,  pWqh, bq, pQh, N_BC * S_LEN, D_MODEL, D_MODEL);
    hgemm_bias<true><<<dim3(12, 10),  gblk, GEMM_SMEM_BYTES>>>(pEHSh, pWkh, bk, pKh, N_BC * T_LEN, D_MODEL, D_MODEL);
    hgemm_bias<true><<<dim3(12, 10),  gblk, GEMM_SMEM_BYTES>>>(pEHSh, pWvh, bv, pVh, N_BC * T_LEN, D_MODEL, D_MODEL);
    // register-softmax HMMA attention
    attn_reg<<<dim3(S_LEN / 32, N_H, N_B), 128, ATTN_SMEM_BYTES>>>(pQh, pKh, pVh, pAOh);
    // output projection (fp32 output into d_out)
    hgemm_bias<false><<<dim3(12, 256), gblk, GEMM_SMEM_BYTES>>>(pAOh, pWoh, bo, out, N_BC * S_LEN, D_MODEL, D_MODEL);
}

// round 8
// speedup vs baseline: 2.2239x; 1.1387x over previous
#include <cuda_runtime.h>
#include <cuda_fp16.h>
#include <stdint.h>
#include <math.h>

#define D_MODEL 1536
#define S_LEN   4096
#define T_LEN   154
#define N_BC    8
#define N_B     2
#define N_H     24
#define DH      64

// ---------------- scratch (device globals; no allocation allowed) ----------------
__device__ __half g_HSh [N_BC * S_LEN * D_MODEL];
__device__ __half g_EHSh[N_BC * T_LEN * D_MODEL];
__device__ __half g_Qh  [N_BC * S_LEN * D_MODEL];
__device__ __half g_Kh  [N_BC * T_LEN * D_MODEL];
__device__ __half g_Vh  [N_BC * T_LEN * D_MODEL];
__device__ __half g_AOh [N_BC * S_LEN * D_MODEL];
__device__ __half g_Wqh[D_MODEL * D_MODEL];
__device__ __half g_Wkh[D_MODEL * D_MODEL];
__device__ __half g_Wvh[D_MODEL * D_MODEL];
__device__ __half g_Woh[D_MODEL * D_MODEL];

// ================= helpers =================
__device__ __forceinline__ uint32_t smem_u32(const void* p) {
    uint32_t a;
    asm("{ .reg .u64 t; cvta.to.shared.u64 t, %1; cvt.u32.u64 %0, t; }" : "=r"(a) : "l"(p));
    return a;
}
__device__ __forceinline__ void ldm_x4(uint32_t* r, uint32_t addr) {
    asm volatile("ldmatrix.sync.aligned.m8n8.x4.shared.b16 {%0,%1,%2,%3}, [%4];"
        : "=r"(r[0]), "=r"(r[1]), "=r"(r[2]), "=r"(r[3]) : "r"(addr));
}
__device__ __forceinline__ void ldm_x4_t(uint32_t* r, uint32_t addr) {
    asm volatile("ldmatrix.sync.aligned.m8n8.x4.trans.shared.b16 {%0,%1,%2,%3}, [%4];"
        : "=r"(r[0]), "=r"(r[1]), "=r"(r[2]), "=r"(r[3]) : "r"(addr));
}
__device__ __forceinline__ void mma16816h(float* d, const uint32_t* a,
                                          uint32_t b0, uint32_t b1) {
    asm volatile(
        "mma.sync.aligned.m16n8k16.row.col.f32.f16.f16.f32 "
        "{%0,%1,%2,%3}, {%4,%5,%6,%7}, {%8,%9}, {%0,%1,%2,%3};"
        : "+f"(d[0]), "+f"(d[1]), "+f"(d[2]), "+f"(d[3])
        : "r"(a[0]), "r"(a[1]), "r"(a[2]), "r"(a[3]), "r"(b0), "r"(b1));
}
__device__ __forceinline__ void cp_async16(uint32_t dst, const void* src) {
    asm volatile("cp.async.cg.shared.global [%0], [%1], 16;" :: "r"(dst), "l"(src));
}
#define CP_COMMIT() asm volatile("cp.async.commit_group;" ::: "memory")
#define CP_WAIT(n)  asm volatile("cp.async.wait_group %0;" :: "n"(n) : "memory")

__device__ __forceinline__ uint32_t packh2(float a, float b) {
    __half2 h = __floats2half2_rn(a, b);
    return *(uint32_t*)&h;
}
__device__ __forceinline__ float ex2a(float x) {
    float y; asm("ex2.approx.f32 %0, %1;" : "=f"(y) : "f"(x)); return y;
}
__device__ __forceinline__ float rcpa(float x) {
    float y; asm("rcp.approx.f32 %0, %1;" : "=f"(y) : "f"(x)); return y;
}

// ================= fp32 -> fp16 convert =================
__global__ void f2h_kernel(const float* __restrict__ x, __half* __restrict__ y, int n4)
{
    int i = blockIdx.x * blockDim.x + threadIdx.x;
    if (i < n4) {
        float4 v = ((const float4*)x)[i];
        __half2* yp = (__half2*)y + i * 2;
        yp[0] = __floats2half2_rn(v.x, v.y);
        yp[1] = __floats2half2_rn(v.z, v.w);
    }
}

// ================= fp16 HGEMM: Y[M,N] = A[M,K] @ B[N,K]^T + bias ====================
#define LDA    40
#define ASTG   (128 * LDA)
#define STG2   (2 * ASTG)
#define NSTAGE 3
#define GEMM_SMEM_BYTES (NSTAGE * STG2 * 2)   // 61440

template<bool HOUT>
__global__ __launch_bounds__(256, 2)
void hgemm_bias(const __half* __restrict__ A, const __half* __restrict__ B,
                const float* __restrict__ bias, void* __restrict__ Yv,
                int M, int N, int K)
{
    extern __shared__ __half sm[];
    const uint32_t sbase = smem_u32(sm);
    const int tid  = threadIdx.x;
    const int wid  = tid >> 5;
    const int lane = tid & 31;
    const int bm   = blockIdx.y * 128;
    const int bn   = blockIdx.x * 128;
    const int wm   = wid & 3;
    const int wn   = wid >> 2;
    const int xrow = lane & 15;
    const int xk   = (lane >> 4) << 3;

    const int crow = tid >> 2;
    const int ccol = (tid & 3) << 3;
    const int ar0 = min(bm + crow,      M - 1);
    const int ar1 = min(bm + crow + 64, M - 1);
    const __half* a0 = A + (size_t)ar0 * K + ccol;
    const __half* a1 = A + (size_t)ar1 * K + ccol;
    const __half* b0 = B + (size_t)(bn + crow) * K + ccol;
    const __half* b1 = B + (size_t)(bn + crow + 64) * K + ccol;
    const uint32_t so0 = (uint32_t)(crow * LDA + ccol) * 2;
    const uint32_t so1 = (uint32_t)((crow + 64) * LDA + ccol) * 2;

    float acc[2][8][4];
    #pragma unroll
    for (int i = 0; i < 2; ++i)
        #pragma unroll
        for (int j = 0; j < 8; ++j)
            #pragma unroll
            for (int q = 0; q < 4; ++q) acc[i][j][q] = 0.f;

    const int NIT = K / 32;

    auto issue = [&](int it) {
        const int s  = it % NSTAGE;
        const int k0 = it * 32;
        uint32_t sa = sbase + (uint32_t)s * STG2 * 2;
        uint32_t sb = sa + ASTG * 2;
        cp_async16(sa + so0, a0 + k0);
        cp_async16(sa + so1, a1 + k0);
        cp_async16(sb + so0, b0 + k0);
        cp_async16(sb + so1, b1 + k0);
    };

    issue(0); CP_COMMIT();
    issue(1); CP_COMMIT();

    for (int it = 0; it < NIT; ++it) {
        if (it == NIT - 1) { CP_WAIT(0); } else { CP_WAIT(1); }
        __syncthreads();
        if (it + 2 < NIT) { issue(it + 2); CP_COMMIT(); }

        const int s = it % NSTAGE;
        const uint32_t sa = sbase + (uint32_t)s * STG2 * 2;
        const uint32_t sb = sa + ASTG * 2;

        #pragma unroll
        for (int kk = 0; kk < 2; ++kk) {
            const int k0 = kk * 16;
            uint32_t af[2][4];
            #pragma unroll
            for (int mf = 0; mf < 2; ++mf)
                ldm_x4(af[mf], sa + (uint32_t)((wm * 32 + mf * 16 + xrow) * LDA + k0 + xk) * 2);
            #pragma unroll
            for (int nf4 = 0; nf4 < 4; ++nf4) {
                uint32_t bf[4];
                ldm_x4(bf, sb + (uint32_t)((wn * 64 + nf4 * 16 + xrow) * LDA + k0 + xk) * 2);
                #pragma unroll
                for (int mf = 0; mf < 2; ++mf) {
                    mma16816h(acc[mf][nf4 * 2],     af[mf], bf[0], bf[2]);
                    mma16816h(acc[mf][nf4 * 2 + 1], af[mf], bf[1], bf[3]);
                }
            }
        }
    }
    __syncthreads();

    const int g  = lane >> 2;
    const int t2 = (lane & 3) << 1;
    #pragma unroll
    for (int mf = 0; mf < 2; ++mf) {
        int r0 = bm + wm * 32 + mf * 16 + g;
        #pragma unroll
        for (int nf = 0; nf < 8; ++nf) {
            int col = bn + wn * 64 + nf * 8 + t2;
            float bv0 = bias[col], bv1 = bias[col + 1];
            float v00 = acc[mf][nf][0] + bv0, v01 = acc[mf][nf][1] + bv1;
            float v10 = acc[mf][nf][2] + bv0, v11 = acc[mf][nf][3] + bv1;
            if (HOUT) {
                __half* Y = (__half*)Yv;
                if (r0 < M)     *(__half2*)(Y + (size_t)r0 * N + col)       = __floats2half2_rn(v00, v01);
                if (r0 + 8 < M) *(__half2*)(Y + (size_t)(r0 + 8) * N + col) = __floats2half2_rn(v10, v11);
            } else {
                float* Y = (float*)Yv;
                if (r0 < M)     *(float2*)(Y + (size_t)r0 * N + col)       = make_float2(v00, v01);
                if (r0 + 8 < M) *(float2*)(Y + (size_t)(r0 + 8) * N + col) = make_float2(v10, v11);
            }
        }
    }
}

// ================= register-softmax HMMA attention (dedup) =======================
// CTA: 128 threads (4 warps), s-tile 64. Warp = 16 s-rows x FULL d=64, all 4 comps.
// No duplicated score work; softmax in registers with ex2.approx, no max-sub.
#define QST 72
#define KST 72
#define KV_MAT   (4 * 32 * KST * 2)              // 18432 B
#define KV_STAGE (2 * KV_MAT)                    // 36864 B (K + V)
#define ATTN_SMEM_BYTES (4 * 64 * QST * 2 + 2 * KV_STAGE)   // 110592

// exp(x*0.125) = exp2(x * 0.125*log2(e))
#define SM_SCALE 0.1803368801f

__global__ __launch_bounds__(128, 2)
void attn_reg(const __half* __restrict__ Q, const __half* __restrict__ K,
              const __half* __restrict__ V, __half* __restrict__ O)
{
    extern __shared__ char smemc[];
    __half* qb = (__half*)smemc;                 // [4][64][QST]
    const uint32_t qbu = smem_u32(qb);
    const uint32_t kvu = qbu + 4 * 64 * QST * 2;

    const int tid  = threadIdx.x;
    const int wid  = tid >> 5;
    const int lane = tid & 31;
    const int b    = blockIdx.z;
    const int h    = blockIdx.y;
    const int s0   = blockIdx.x * 64;

    const int sbase = wid * 16;
    const int xrow  = lane & 15;
    const int xk    = (lane >> 4) << 3;
    const int g     = lane >> 2;
    const int q2    = (lane & 3) << 1;

    // ---- load Q tile: 4c x 64s x 64d = 2048 uint4, 16 per thread ----
    #pragma unroll
    for (int it = 0; it < 16; ++it) {
        int i  = tid + it * 128;
        int cc = i >> 9, r = i & 511, si = r >> 3, d8 = (r & 7) << 3;
        const __half* gp = Q + ((size_t)(cc * N_B + b) * S_LEN + s0 + si) * D_MODEL + h * DH + d8;
        *(uint4*)(qb + (cc * 64 + si) * QST + d8) = *(const uint4*)gp;
    }

    const int NCH = (T_LEN + 31) / 32;   // 5

    auto issue = [&](int ch) {
        const int t0 = ch * 32;
        const uint32_t st = kvu + (uint32_t)(ch & 1) * KV_STAGE;
        #pragma unroll
        for (int it = 0; it < 8; ++it) {
            int i  = tid + it * 128;
            int cc = i >> 8, r = i & 255, tj = r >> 3, d8 = (r & 7) << 3;
            int t = min(t0 + tj, T_LEN - 1);     // clamp; weights zeroed for t>=T_LEN
            size_t go = ((size_t)(cc * N_B + b) * T_LEN + t) * D_MODEL + h * DH + d8;
            uint32_t so = (uint32_t)((cc * 32 + tj) * KST + d8) * 2;
            cp_async16(st + so, K + go);
            cp_async16(st + KV_MAT + so, V + go);
        }
    };

    issue(0); CP_COMMIT();
    issue(1); CP_COMMIT();

    float oacc[4][8][4];
    #pragma unroll
    for (int c = 0; c < 4; ++c)
        #pragma unroll
        for (int j = 0; j < 8; ++j)
            #pragma unroll
            for (int e = 0; e < 4; ++e) oacc[c][j][e] = 0.f;
    float rsum[2][4];
    #pragma unroll
    for (int r = 0; r < 2; ++r)
        #pragma unroll
        for (int c = 0; c < 4; ++c) rsum[r][c] = 0.f;

    for (int ch = 0; ch < NCH; ++ch) {
        if (ch == NCH - 1) { CP_WAIT(0); } else { CP_WAIT(1); }
        __syncthreads();

        const uint32_t kbu = kvu + (uint32_t)(ch & 1) * KV_STAGE;
        const uint32_t vbu = kbu + KV_MAT;

        // ---- scores: sacc[c][j n8][e], tile = 16s x 32t per warp ----
        float sacc[4][4][4];
        #pragma unroll
        for (int c = 0; c < 4; ++c)
            #pragma unroll
            for (int j = 0; j < 4; ++j)
                #pragma unroll
                for (int e = 0; e < 4; ++e) sacc[c][j][e] = 0.f;

        #pragma unroll
        for (int c = 0; c < 4; ++c) {
            #pragma unroll
            for (int kk = 0; kk < 4; ++kk) {
                uint32_t af[4];
                ldm_x4(af, qbu + (uint32_t)((c * 64 + sbase + xrow) * QST + kk * 16 + xk) * 2);
                #pragma unroll
                for (int nf16 = 0; nf16 < 2; ++nf16) {
                    uint32_t bf[4];
                    ldm_x4(bf, kbu + (uint32_t)((c * 32 + nf16 * 16 + xrow) * KST + kk * 16 + xk) * 2);
                    mma16816h(sacc[c][nf16 * 2],     af, bf[0], bf[2]);
                    mma16816h(sacc[c][nf16 * 2 + 1], af, bf[1], bf[3]);
                }
            }
        }

        // ---- per k16-group: register softmax (no max-sub) + AV MMA ----
        #pragma unroll
        for (int kk = 0; kk < 2; ++kk) {
            uint32_t wf[4][4];
            #pragma unroll
            for (int jh = 0; jh < 2; ++jh) {
                const int j = kk * 2 + jh;
                float wt[4][4];
                #pragma unroll
                for (int e = 0; e < 4; ++e) {
                    int col = ch * 32 + j * 8 + q2 + (e & 1);
                    float e0 = ex2a(sacc[0][j][e] * SM_SCALE);
                    float e1 = ex2a(sacc[1][j][e] * SM_SCALE);
                    float e2 = ex2a(sacc[2][j][e] * SM_SCALE);
                    float e3 = ex2a(sacc[3][j][e] * SM_SCALE);
                    float inv = (col < T_LEN) ? rcpa(e0 + e1 + e2 + e3) : 0.f;
                    e0 *= inv; e1 *= inv; e2 *= inv; e3 *= inv;
                    int rr = e >> 1;
                    rsum[rr][0] += e0; rsum[rr][1] += e1;
                    rsum[rr][2] += e2; rsum[rr][3] += e3;
                    wt[0][e] = e0; wt[1][e] = e1; wt[2][e] = e2; wt[3][e] = e3;
                }
                #pragma unroll
                for (int c = 0; c < 4; ++c) {
                    wf[c][jh * 2 + 0] = packh2(wt[c][0], wt[c][1]);
                    wf[c][jh * 2 + 1] = packh2(wt[c][2], wt[c][3]);
                }
            }
            #pragma unroll
            for (int c = 0; c < 4; ++c) {
                #pragma unroll
                for (int nf16 = 0; nf16 < 4; ++nf16) {
                    uint32_t bf[4];
                    ldm_x4_t(bf, vbu + (uint32_t)((c * 32 + kk * 16 + xrow) * KST + nf16 * 16 + xk) * 2);
                    mma16816h(oacc[c][nf16 * 2],     wf[c], bf[0], bf[1]);
                    mma16816h(oacc[c][nf16 * 2 + 1], wf[c], bf[2], bf[3]);
                }
            }
        }
        __syncthreads();
        if (ch + 2 < NCH) { issue(ch + 2); CP_COMMIT(); }
    }

    // ---- finalize row sums across quad lanes ----
    #pragma unroll
    for (int x = 1; x <= 2; x <<= 1)
        #pragma unroll
        for (int r = 0; r < 2; ++r)
            #pragma unroll
            for (int c = 0; c < 4; ++c)
                rsum[r][c] += __shfl_xor_sync(0xffffffffu, rsum[r][c], x);

    // ---- renormalize and store ----
    #pragma unroll
    for (int c = 0; c < 4; ++c) {
        float inv0 = 1.f / (rsum[0][c] + 1e-8f);
        float inv1 = 1.f / (rsum[1][c] + 1e-8f);
        int row0 = s0 + sbase + g;
        __half* gp0 = O + ((size_t)(c * N_B + b) * S_LEN + row0) * D_MODEL + h * DH + q2;
        __half* gp1 = gp0 + (size_t)8 * D_MODEL;
        #pragma unroll
        for (int j = 0; j < 8; ++j) {
            *(__half2*)(gp0 + j * 8) = __floats2half2_rn(oacc[c][j][0] * inv0, oacc[c][j][1] * inv0);
            *(__half2*)(gp1 + j * 8) = __floats2half2_rn(oacc[c][j][2] * inv1, oacc[c][j][3] * inv1);
        }
    }
}

// ---------------- launch ----------------
extern "C" void kernel_launch(void* const* d_in, const int* in_sizes, int n_in,
                              void* d_out, int out_size)
{
    const float* HS  = (const float*)d_in[0];
    const float* EHS = (const float*)d_in[1];
    const float* Wq  = (const float*)d_in[2];
    const float* bq  = (const float*)d_in[3];
    const float* Wk  = (const float*)d_in[4];
    const float* bk  = (const float*)d_in[5];
    const float* Wv  = (const float*)d_in[6];
    const float* bv  = (const float*)d_in[7];
    const float* Wo  = (const float*)d_in[8];
    const float* bo  = (const float*)d_in[9];
    float* out = (float*)d_out;

    __half *pHSh, *pEHSh, *pQh, *pKh, *pVh, *pAOh, *pWqh, *pWkh, *pWvh, *pWoh;
    cudaGetSymbolAddress((void**)&pHSh,  g_HSh);
    cudaGetSymbolAddress((void**)&pEHSh, g_EHSh);
    cudaGetSymbolAddress((void**)&pQh,   g_Qh);
    cudaGetSymbolAddress((void**)&pKh,   g_Kh);
    cudaGetSymbolAddress((void**)&pVh,   g_Vh);
    cudaGetSymbolAddress((void**)&pAOh,  g_AOh);
    cudaGetSymbolAddress((void**)&pWqh,  g_Wqh);
    cudaGetSymbolAddress((void**)&pWkh,  g_Wkh);
    cudaGetSymbolAddress((void**)&pWvh,  g_Wvh);
    cudaGetSymbolAddress((void**)&pWoh,  g_Woh);

    cudaFuncSetAttribute(hgemm_bias<true>,  cudaFuncAttributeMaxDynamicSharedMemorySize, GEMM_SMEM_BYTES);
    cudaFuncSetAttribute(hgemm_bias<false>, cudaFuncAttributeMaxDynamicSharedMemorySize, GEMM_SMEM_BYTES);
    cudaFuncSetAttribute(attn_reg, cudaFuncAttributeMaxDynamicSharedMemorySize, ATTN_SMEM_BYTES);

    const int nHS = N_BC * S_LEN * D_MODEL / 4;
    const int nEH = N_BC * T_LEN * D_MODEL / 4;
    const int nW  = D_MODEL * D_MODEL / 4;
    f2h_kernel<<<(nHS + 255) / 256, 256>>>(HS,  pHSh,  nHS);
    f2h_kernel<<<(nEH + 255) / 256, 256>>>(EHS, pEHSh, nEH);
    f2h_kernel<<<(nW  + 255) / 256, 256>>>(Wq,  pWqh,  nW);
    f2h_kernel<<<(nW  + 255) / 256, 256>>>(Wk,  pWkh,  nW);
    f2h_kernel<<<(nW  + 255) / 256, 256>>>(Wv,  pWvh,  nW);
    f2h_kernel<<<(nW  + 255) / 256, 256>>>(Wo,  pWoh,  nW);

    dim3 gblk(256);
    // projections (fp16 outputs)
    hgemm_bias<true><<<dim3(12, 256), gblk, GEMM_SMEM_BYTES>>>(pHSh,  pWqh, bq, pQh, N_BC * S_LEN, D_MODEL, D_MODEL);
    hgemm_bias<true><<<dim3(12, 10),  gblk, GEMM_SMEM_BYTES>>>(pEHSh, pWkh, bk, pKh, N_BC * T_LEN, D_MODEL, D_MODEL);
    hgemm_bias<true><<<dim3(12, 10),  gblk, GEMM_SMEM_BYTES>>>(pEHSh, pWvh, bv, pVh, N_BC * T_LEN, D_MODEL, D_MODEL);
    // dedup register-softmax HMMA attention (s-tile 64)
    attn_reg<<<dim3(S_LEN / 64, N_H, N_B), 128, ATTN_SMEM_BYTES>>>(pQh, pKh, pVh, pAOh);
    // output projection (fp32 output into d_out)
    hgemm_bias<false><<<dim3(12, 256), gblk, GEMM_SMEM_BYTES>>>(pAOh, pWoh, bo, out, N_BC * S_LEN, D_MODEL, D_MODEL);
}

// round 9
// speedup vs baseline: 2.2409x; 1.0076x over previous
#include <cuda_runtime.h>
#include <cuda_fp16.h>
#include <stdint.h>
#include <math.h>

#define D_MODEL 1536
#define S_LEN   4096
#define T_LEN   154
#define N_BC    8
#define N_B     2
#define N_H     24
#define DH      64

// ---------------- scratch (device globals; no allocation allowed) ----------------
__device__ __half g_HSh [N_BC * S_LEN * D_MODEL];
__device__ __half g_EHSh[N_BC * T_LEN * D_MODEL];
__device__ __half g_Qh  [N_BC * S_LEN * D_MODEL];
__device__ __half g_Kh  [N_BC * T_LEN * D_MODEL];
__device__ __half g_Vh  [N_BC * T_LEN * D_MODEL];
__device__ __half g_AOh [N_BC * S_LEN * D_MODEL];
__device__ __half g_Wqh[D_MODEL * D_MODEL];
__device__ __half g_Wkh[D_MODEL * D_MODEL];
__device__ __half g_Wvh[D_MODEL * D_MODEL];
__device__ __half g_Woh[D_MODEL * D_MODEL];

// ================= helpers =================
__device__ __forceinline__ uint32_t smem_u32(const void* p) {
    uint32_t a;
    asm("{ .reg .u64 t; cvta.to.shared.u64 t, %1; cvt.u32.u64 %0, t; }" : "=r"(a) : "l"(p));
    return a;
}
__device__ __forceinline__ void ldm_x4(uint32_t* r, uint32_t addr) {
    asm volatile("ldmatrix.sync.aligned.m8n8.x4.shared.b16 {%0,%1,%2,%3}, [%4];"
        : "=r"(r[0]), "=r"(r[1]), "=r"(r[2]), "=r"(r[3]) : "r"(addr));
}
__device__ __forceinline__ void ldm_x4_t(uint32_t* r, uint32_t addr) {
    asm volatile("ldmatrix.sync.aligned.m8n8.x4.trans.shared.b16 {%0,%1,%2,%3}, [%4];"
        : "=r"(r[0]), "=r"(r[1]), "=r"(r[2]), "=r"(r[3]) : "r"(addr));
}
__device__ __forceinline__ void mma16816h(float* d, const uint32_t* a,
                                          uint32_t b0, uint32_t b1) {
    asm volatile(
        "mma.sync.aligned.m16n8k16.row.col.f32.f16.f16.f32 "
        "{%0,%1,%2,%3}, {%4,%5,%6,%7}, {%8,%9}, {%0,%1,%2,%3};"
        : "+f"(d[0]), "+f"(d[1]), "+f"(d[2]), "+f"(d[3])
        : "r"(a[0]), "r"(a[1]), "r"(a[2]), "r"(a[3]), "r"(b0), "r"(b1));
}
__device__ __forceinline__ void cp_async16(uint32_t dst, const void* src) {
    asm volatile("cp.async.cg.shared.global [%0], [%1], 16;" :: "r"(dst), "l"(src));
}
#define CP_COMMIT() asm volatile("cp.async.commit_group;" ::: "memory")
#define CP_WAIT(n)  asm volatile("cp.async.wait_group %0;" :: "n"(n) : "memory")

__device__ __forceinline__ uint32_t packh2(float a, float b) {
    __half2 h = __floats2half2_rn(a, b);
    return *(uint32_t*)&h;
}
__device__ __forceinline__ float ex2a(float x) {
    float y; asm("ex2.approx.f32 %0, %1;" : "=f"(y) : "f"(x)); return y;
}
__device__ __forceinline__ float rcpa(float x) {
    float y; asm("rcp.approx.f32 %0, %1;" : "=f"(y) : "f"(x)); return y;
}

// ================= fp32 -> fp16 convert =================
__global__ void f2h_kernel(const float* __restrict__ x, __half* __restrict__ y, int n4)
{
    int i = blockIdx.x * blockDim.x + threadIdx.x;
    if (i < n4) {
        float4 v = ((const float4*)x)[i];
        __half2* yp = (__half2*)y + i * 2;
        yp[0] = __floats2half2_rn(v.x, v.y);
        yp[1] = __floats2half2_rn(v.z, v.w);
    }
}

// batched weight convert: blockIdx.y selects which matrix
__global__ void f2h4_kernel(const float* __restrict__ x0, const float* __restrict__ x1,
                            const float* __restrict__ x2, const float* __restrict__ x3,
                            __half* __restrict__ y0, __half* __restrict__ y1,
                            __half* __restrict__ y2, __half* __restrict__ y3, int n4)
{
    const float* x; __half* y;
    switch (blockIdx.y) {
        case 0:  x = x0; y = y0; break;
        case 1:  x = x1; y = y1; break;
        case 2:  x = x2; y = y2; break;
        default: x = x3; y = y3; break;
    }
    int i = blockIdx.x * blockDim.x + threadIdx.x;
    if (i < n4) {
        float4 v = ((const float4*)x)[i];
        __half2* yp = (__half2*)y + i * 2;
        yp[0] = __floats2half2_rn(v.x, v.y);
        yp[1] = __floats2half2_rn(v.z, v.w);
    }
}

// ================= fp16 HGEMM: Y[M,N] = A[M,K] @ B[N,K]^T + bias ====================
// Optional second problem (B2/bias2/Y2) selected when blockIdx.x >= nx1 (K/V merge).
#define LDA    40
#define ASTG   (128 * LDA)
#define STG2   (2 * ASTG)
#define NSTAGE 3
#define GEMM_SMEM_BYTES (NSTAGE * STG2 * 2)   // 61440

template<bool HOUT>
__global__ __launch_bounds__(256, 2)
void hgemm_bias(const __half* __restrict__ A, const __half* __restrict__ B,
                const float* __restrict__ bias, void* __restrict__ Yv,
                const __half* __restrict__ B2, const float* __restrict__ bias2,
                void* __restrict__ Yv2, int nx1,
                int M, int N, int K)
{
    extern __shared__ __half sm[];
    const uint32_t sbase = smem_u32(sm);
    const int tid  = threadIdx.x;
    const int wid  = tid >> 5;
    const int lane = tid & 31;

    const __half* Bp = B;
    const float*  bp = bias;
    void*         Yp = Yv;
    int bx = blockIdx.x;
    if (B2 != nullptr && bx >= nx1) { Bp = B2; bp = bias2; Yp = Yv2; bx -= nx1; }

    const int bm   = blockIdx.y * 128;
    const int bn   = bx * 128;
    const int wm   = wid & 3;
    const int wn   = wid >> 2;
    const int xrow = lane & 15;
    const int xk   = (lane >> 4) << 3;

    const int crow = tid >> 2;
    const int ccol = (tid & 3) << 3;
    const int ar0 = min(bm + crow,      M - 1);
    const int ar1 = min(bm + crow + 64, M - 1);
    const __half* a0 = A + (size_t)ar0 * K + ccol;
    const __half* a1 = A + (size_t)ar1 * K + ccol;
    const __half* b0 = Bp + (size_t)(bn + crow) * K + ccol;
    const __half* b1 = Bp + (size_t)(bn + crow + 64) * K + ccol;
    const uint32_t so0 = (uint32_t)(crow * LDA + ccol) * 2;
    const uint32_t so1 = (uint32_t)((crow + 64) * LDA + ccol) * 2;

    float acc[2][8][4];
    #pragma unroll
    for (int i = 0; i < 2; ++i)
        #pragma unroll
        for (int j = 0; j < 8; ++j)
            #pragma unroll
            for (int q = 0; q < 4; ++q) acc[i][j][q] = 0.f;

    const int NIT = K / 32;

    auto issue = [&](int it) {
        const int s  = it % NSTAGE;
        const int k0 = it * 32;
        uint32_t sa = sbase + (uint32_t)s * STG2 * 2;
        uint32_t sb = sa + ASTG * 2;
        cp_async16(sa + so0, a0 + k0);
        cp_async16(sa + so1, a1 + k0);
        cp_async16(sb + so0, b0 + k0);
        cp_async16(sb + so1, b1 + k0);
    };

    issue(0); CP_COMMIT();
    issue(1); CP_COMMIT();

    for (int it = 0; it < NIT; ++it) {
        if (it == NIT - 1) { CP_WAIT(0); } else { CP_WAIT(1); }
        __syncthreads();
        if (it + 2 < NIT) { issue(it + 2); CP_COMMIT(); }

        const int s = it % NSTAGE;
        const uint32_t sa = sbase + (uint32_t)s * STG2 * 2;
        const uint32_t sb = sa + ASTG * 2;

        #pragma unroll
        for (int kk = 0; kk < 2; ++kk) {
            const int k0 = kk * 16;
            uint32_t af[2][4];
            #pragma unroll
            for (int mf = 0; mf < 2; ++mf)
                ldm_x4(af[mf], sa + (uint32_t)((wm * 32 + mf * 16 + xrow) * LDA + k0 + xk) * 2);
            #pragma unroll
            for (int nf4 = 0; nf4 < 4; ++nf4) {
                uint32_t bf[4];
                ldm_x4(bf, sb + (uint32_t)((wn * 64 + nf4 * 16 + xrow) * LDA + k0 + xk) * 2);
                #pragma unroll
                for (int mf = 0; mf < 2; ++mf) {
                    mma16816h(acc[mf][nf4 * 2],     af[mf], bf[0], bf[2]);
                    mma16816h(acc[mf][nf4 * 2 + 1], af[mf], bf[1], bf[3]);
                }
            }
        }
    }
    __syncthreads();

    const int g  = lane >> 2;
    const int t2 = (lane & 3) << 1;
    #pragma unroll
    for (int mf = 0; mf < 2; ++mf) {
        int r0 = bm + wm * 32 + mf * 16 + g;
        #pragma unroll
        for (int nf = 0; nf < 8; ++nf) {
            int col = bn + wn * 64 + nf * 8 + t2;
            float bv0 = bp[col], bv1 = bp[col + 1];
            float v00 = acc[mf][nf][0] + bv0, v01 = acc[mf][nf][1] + bv1;
            float v10 = acc[mf][nf][2] + bv0, v11 = acc[mf][nf][3] + bv1;
            if (HOUT) {
                __half* Y = (__half*)Yp;
                if (r0 < M)     *(__half2*)(Y + (size_t)r0 * N + col)       = __floats2half2_rn(v00, v01);
                if (r0 + 8 < M) *(__half2*)(Y + (size_t)(r0 + 8) * N + col) = __floats2half2_rn(v10, v11);
            } else {
                float* Y = (float*)Yp;
                if (r0 < M)     *(float2*)(Y + (size_t)r0 * N + col)       = make_float2(v00, v01);
                if (r0 + 8 < M) *(float2*)(Y + (size_t)(r0 + 8) * N + col) = make_float2(v10, v11);
            }
        }
    }
}

// ================= register-softmax HMMA attention (dedup, e3-baseline) ===========
#define QST 72
#define KST 72
#define KV_MAT   (4 * 32 * KST * 2)              // 18432 B
#define KV_STAGE (2 * KV_MAT)                    // 36864 B (K + V)
#define ATTN_SMEM_BYTES (4 * 64 * QST * 2 + 2 * KV_STAGE)   // 110592

// exp(x*0.125) = exp2(x * 0.125*log2(e))
#define SM_SCALE 0.1803368801f

__global__ __launch_bounds__(128, 2)
void attn_reg(const __half* __restrict__ Q, const __half* __restrict__ K,
              const __half* __restrict__ V, __half* __restrict__ O)
{
    extern __shared__ char smemc[];
    __half* qb = (__half*)smemc;                 // [4][64][QST]
    const uint32_t qbu = smem_u32(qb);
    const uint32_t kvu = qbu + 4 * 64 * QST * 2;

    const int tid  = threadIdx.x;
    const int wid  = tid >> 5;
    const int lane = tid & 31;
    const int b    = blockIdx.z;
    const int h    = blockIdx.y;
    const int s0   = blockIdx.x * 64;

    const int sbase = wid * 16;
    const int xrow  = lane & 15;
    const int xk    = (lane >> 4) << 3;
    const int g     = lane >> 2;
    const int q2    = (lane & 3) << 1;

    // ---- load Q tile: 4c x 64s x 64d ----
    #pragma unroll
    for (int it = 0; it < 16; ++it) {
        int i  = tid + it * 128;
        int cc = i >> 9, r = i & 511, si = r >> 3, d8 = (r & 7) << 3;
        const __half* gp = Q + ((size_t)(cc * N_B + b) * S_LEN + s0 + si) * D_MODEL + h * DH + d8;
        *(uint4*)(qb + (cc * 64 + si) * QST + d8) = *(const uint4*)gp;
    }

    const int NCH = (T_LEN + 31) / 32;   // 5

    auto issue = [&](int ch) {
        const int t0 = ch * 32;
        const uint32_t st = kvu + (uint32_t)(ch & 1) * KV_STAGE;
        #pragma unroll
        for (int it = 0; it < 8; ++it) {
            int i  = tid + it * 128;
            int cc = i >> 8, r = i & 255, tj = r >> 3, d8 = (r & 7) << 3;
            int t = min(t0 + tj, T_LEN - 1);     // clamp; weights zeroed for t>=T_LEN
            size_t go = ((size_t)(cc * N_B + b) * T_LEN + t) * D_MODEL + h * DH + d8;
            uint32_t so = (uint32_t)((cc * 32 + tj) * KST + d8) * 2;
            cp_async16(st + so, K + go);
            cp_async16(st + KV_MAT + so, V + go);
        }
    };

    issue(0); CP_COMMIT();
    issue(1); CP_COMMIT();

    float oacc[4][8][4];
    #pragma unroll
    for (int c = 0; c < 4; ++c)
        #pragma unroll
        for (int j = 0; j < 8; ++j)
            #pragma unroll
            for (int e = 0; e < 4; ++e) oacc[c][j][e] = 0.f;
    float rsum[2][4];
    #pragma unroll
    for (int r = 0; r < 2; ++r)
        #pragma unroll
        for (int c = 0; c < 4; ++c) rsum[r][c] = 0.f;

    for (int ch = 0; ch < NCH; ++ch) {
        if (ch == NCH - 1) { CP_WAIT(0); } else { CP_WAIT(1); }
        __syncthreads();

        const uint32_t kbu = kvu + (uint32_t)(ch & 1) * KV_STAGE;
        const uint32_t vbu = kbu + KV_MAT;

        // ---- scores: 16s x 32t per warp, all 4 components ----
        float sacc[4][4][4];
        #pragma unroll
        for (int c = 0; c < 4; ++c)
            #pragma unroll
            for (int j = 0; j < 4; ++j)
                #pragma unroll
                for (int e = 0; e < 4; ++e) sacc[c][j][e] = 0.f;

        #pragma unroll
        for (int c = 0; c < 4; ++c) {
            #pragma unroll
            for (int kk = 0; kk < 4; ++kk) {
                uint32_t af[4];
                ldm_x4(af, qbu + (uint32_t)((c * 64 + sbase + xrow) * QST + kk * 16 + xk) * 2);
                #pragma unroll
                for (int nf16 = 0; nf16 < 2; ++nf16) {
                    uint32_t bf[4];
                    ldm_x4(bf, kbu + (uint32_t)((c * 32 + nf16 * 16 + xrow) * KST + kk * 16 + xk) * 2);
                    mma16816h(sacc[c][nf16 * 2],     af, bf[0], bf[2]);
                    mma16816h(sacc[c][nf16 * 2 + 1], af, bf[1], bf[3]);
                }
            }
        }

        // ---- register softmax (component 3 as baseline: 3 ex2 instead of 4) + AV ----
        #pragma unroll
        for (int kk = 0; kk < 2; ++kk) {
            uint32_t wf[4][4];
            #pragma unroll
            for (int jh = 0; jh < 2; ++jh) {
                const int j = kk * 2 + jh;
                float wt[4][4];
                #pragma unroll
                for (int e = 0; e < 4; ++e) {
                    int col = ch * 32 + j * 8 + q2 + (e & 1);
                    float t3 = sacc[3][j][e] * SM_SCALE;
                    float e0 = ex2a(fmaf(sacc[0][j][e], SM_SCALE, -t3));
                    float e1 = ex2a(fmaf(sacc[1][j][e], SM_SCALE, -t3));
                    float e2 = ex2a(fmaf(sacc[2][j][e], SM_SCALE, -t3));
                    float inv = (col < T_LEN) ? rcpa(e0 + e1 + e2 + 1.f) : 0.f;
                    e0 *= inv; e1 *= inv; e2 *= inv;
                    int rr = e >> 1;
                    rsum[rr][0] += e0; rsum[rr][1] += e1;
                    rsum[rr][2] += e2; rsum[rr][3] += inv;
                    wt[0][e] = e0; wt[1][e] = e1; wt[2][e] = e2; wt[3][e] = inv;
                }
                #pragma unroll
                for (int c = 0; c < 4; ++c) {
                    wf[c][jh * 2 + 0] = packh2(wt[c][0], wt[c][1]);
                    wf[c][jh * 2 + 1] = packh2(wt[c][2], wt[c][3]);
                }
            }
            #pragma unroll
            for (int c = 0; c < 4; ++c) {
                #pragma unroll
                for (int nf16 = 0; nf16 < 4; ++nf16) {
                    uint32_t bf[4];
                    ldm_x4_t(bf, vbu + (uint32_t)((c * 32 + kk * 16 + xrow) * KST + nf16 * 16 + xk) * 2);
                    mma16816h(oacc[c][nf16 * 2],     wf[c], bf[0], bf[1]);
                    mma16816h(oacc[c][nf16 * 2 + 1], wf[c], bf[2], bf[3]);
                }
            }
        }
        __syncthreads();
        if (ch + 2 < NCH) { issue(ch + 2); CP_COMMIT(); }
    }

    // ---- finalize row sums across quad lanes ----
    #pragma unroll
    for (int x = 1; x <= 2; x <<= 1)
        #pragma unroll
        for (int r = 0; r < 2; ++r)
            #pragma unroll
            for (int c = 0; c < 4; ++c)
                rsum[r][c] += __shfl_xor_sync(0xffffffffu, rsum[r][c], x);

    // ---- renormalize and store ----
    #pragma unroll
    for (int c = 0; c < 4; ++c) {
        float inv0 = 1.f / (rsum[0][c] + 1e-8f);
        float inv1 = 1.f / (rsum[1][c] + 1e-8f);
        int row0 = s0 + sbase + g;
        __half* gp0 = O + ((size_t)(c * N_B + b) * S_LEN + row0) * D_MODEL + h * DH + q2;
        __half* gp1 = gp0 + (size_t)8 * D_MODEL;
        #pragma unroll
        for (int j = 0; j < 8; ++j) {
            *(__half2*)(gp0 + j * 8) = __floats2half2_rn(oacc[c][j][0] * inv0, oacc[c][j][1] * inv0);
            *(__half2*)(gp1 + j * 8) = __floats2half2_rn(oacc[c][j][2] * inv1, oacc[c][j][3] * inv1);
        }
    }
}

// ---------------- launch ----------------
extern "C" void kernel_launch(void* const* d_in, const int* in_sizes, int n_in,
                              void* d_out, int out_size)
{
    const float* HS  = (const float*)d_in[0];
    const float* EHS = (const float*)d_in[1];
    const float* Wq  = (const float*)d_in[2];
    const float* bq  = (const float*)d_in[3];
    const float* Wk  = (const float*)d_in[4];
    const float* bk  = (const float*)d_in[5];
    const float* Wv  = (const float*)d_in[6];
    const float* bv  = (const float*)d_in[7];
    const float* Wo  = (const float*)d_in[8];
    const float* bo  = (const float*)d_in[9];
    float* out = (float*)d_out;

    __half *pHSh, *pEHSh, *pQh, *pKh, *pVh, *pAOh, *pWqh, *pWkh, *pWvh, *pWoh;
    cudaGetSymbolAddress((void**)&pHSh,  g_HSh);
    cudaGetSymbolAddress((void**)&pEHSh, g_EHSh);
    cudaGetSymbolAddress((void**)&pQh,   g_Qh);
    cudaGetSymbolAddress((void**)&pKh,   g_Kh);
    cudaGetSymbolAddress((void**)&pVh,   g_Vh);
    cudaGetSymbolAddress((void**)&pAOh,  g_AOh);
    cudaGetSymbolAddress((void**)&pWqh,  g_Wqh);
    cudaGetSymbolAddress((void**)&pWkh,  g_Wkh);
    cudaGetSymbolAddress((void**)&pWvh,  g_Wvh);
    cudaGetSymbolAddress((void**)&pWoh,  g_Woh);

    cudaFuncSetAttribute(hgemm_bias<true>,  cudaFuncAttributeMaxDynamicSharedMemorySize, GEMM_SMEM_BYTES);
    cudaFuncSetAttribute(hgemm_bias<false>, cudaFuncAttributeMaxDynamicSharedMemorySize, GEMM_SMEM_BYTES);
    cudaFuncSetAttribute(attn_reg, cudaFuncAttributeMaxDynamicSharedMemorySize, ATTN_SMEM_BYTES);

    const int nHS = N_BC * S_LEN * D_MODEL / 4;
    const int nEH = N_BC * T_LEN * D_MODEL / 4;
    const int nW  = D_MODEL * D_MODEL / 4;
    f2h_kernel<<<(nHS + 255) / 256, 256>>>(HS,  pHSh,  nHS);
    f2h_kernel<<<(nEH + 255) / 256, 256>>>(EHS, pEHSh, nEH);
    f2h4_kernel<<<dim3((nW + 255) / 256, 4), 256>>>(Wq, Wk, Wv, Wo,
                                                    pWqh, pWkh, pWvh, pWoh, nW);

    dim3 gblk(256);
    // Q projection (fp16 out)
    hgemm_bias<true><<<dim3(12, 256), gblk, GEMM_SMEM_BYTES>>>(
        pHSh, pWqh, bq, pQh, nullptr, nullptr, nullptr, 0,
        N_BC * S_LEN, D_MODEL, D_MODEL);
    // merged K + V projections (fp16 out): bx<12 -> K, bx>=12 -> V
    hgemm_bias<true><<<dim3(24, 10), gblk, GEMM_SMEM_BYTES>>>(
        pEHSh, pWkh, bk, pKh, pWvh, bv, pVh, 12,
        N_BC * T_LEN, D_MODEL, D_MODEL);
    // dedup register-softmax HMMA attention (s-tile 64)
    attn_reg<<<dim3(S_LEN / 64, N_H, N_B), 128, ATTN_SMEM_BYTES>>>(pQh, pKh, pVh, pAOh);
    // output projection (fp32 output into d_out)
    hgemm_bias<false><<<dim3(12, 256), gblk, GEMM_SMEM_BYTES>>>(
        pAOh, pWoh, bo, out, nullptr, nullptr, nullptr, 0,
        N_BC * S_LEN, D_MODEL, D_MODEL);
}

// round 10
// speedup vs baseline: 2.5057x; 1.1182x over previous
#include <cuda_runtime.h>
#include <cuda_fp16.h>
#include <stdint.h>
#include <math.h>

#define D_MODEL 1536
#define S_LEN   4096
#define T_LEN   154
#define N_BC    8
#define N_B     2
#define N_H     24
#define DH      64

// ---------------- scratch (device globals; no allocation allowed) ----------------
__device__ __half g_HSh [N_BC * S_LEN * D_MODEL];
__device__ __half g_EHSh[N_BC * T_LEN * D_MODEL];
__device__ __half g_Qh  [N_BC * S_LEN * D_MODEL];
__device__ __half g_Kh  [N_BC * T_LEN * D_MODEL];
__device__ __half g_Vh  [N_BC * T_LEN * D_MODEL];
__device__ __half g_AOh [N_BC * S_LEN * D_MODEL];
__device__ __half g_Wqh[D_MODEL * D_MODEL];
__device__ __half g_Wkh[D_MODEL * D_MODEL];
__device__ __half g_Wvh[D_MODEL * D_MODEL];
__device__ __half g_Woh[D_MODEL * D_MODEL];

// ================= helpers =================
__device__ __forceinline__ uint32_t smem_u32(const void* p) {
    uint32_t a;
    asm("{ .reg .u64 t; cvta.to.shared.u64 t, %1; cvt.u32.u64 %0, t; }" : "=r"(a) : "l"(p));
    return a;
}
__device__ __forceinline__ void ldm_x4(uint32_t* r, uint32_t addr) {
    asm volatile("ldmatrix.sync.aligned.m8n8.x4.shared.b16 {%0,%1,%2,%3}, [%4];"
        : "=r"(r[0]), "=r"(r[1]), "=r"(r[2]), "=r"(r[3]) : "r"(addr));
}
__device__ __forceinline__ void ldm_x4_t(uint32_t* r, uint32_t addr) {
    asm volatile("ldmatrix.sync.aligned.m8n8.x4.trans.shared.b16 {%0,%1,%2,%3}, [%4];"
        : "=r"(r[0]), "=r"(r[1]), "=r"(r[2]), "=r"(r[3]) : "r"(addr));
}
__device__ __forceinline__ void mma16816h(float* d, const uint32_t* a,
                                          uint32_t b0, uint32_t b1) {
    asm volatile(
        "mma.sync.aligned.m16n8k16.row.col.f32.f16.f16.f32 "
        "{%0,%1,%2,%3}, {%4,%5,%6,%7}, {%8,%9}, {%0,%1,%2,%3};"
        : "+f"(d[0]), "+f"(d[1]), "+f"(d[2]), "+f"(d[3])
        : "r"(a[0]), "r"(a[1]), "r"(a[2]), "r"(a[3]), "r"(b0), "r"(b1));
}
__device__ __forceinline__ void cp_async16(uint32_t dst, const void* src) {
    asm volatile("cp.async.cg.shared.global [%0], [%1], 16;" :: "r"(dst), "l"(src));
}
#define CP_COMMIT() asm volatile("cp.async.commit_group;" ::: "memory")
#define CP_WAIT(n)  asm volatile("cp.async.wait_group %0;" :: "n"(n) : "memory")

__device__ __forceinline__ uint32_t packh2(float a, float b) {
    __half2 h = __floats2half2_rn(a, b);
    return *(uint32_t*)&h;
}
__device__ __forceinline__ float ex2a(float x) {
    float y; asm("ex2.approx.f32 %0, %1;" : "=f"(y) : "f"(x)); return y;
}
__device__ __forceinline__ float rcpa(float x) {
    float y; asm("rcp.approx.f32 %0, %1;" : "=f"(y) : "f"(x)); return y;
}

// ================= fp32 -> fp16 convert =================
__global__ void f2h_kernel(const float* __restrict__ x, __half* __restrict__ y, int n4)
{
    int i = blockIdx.x * blockDim.x + threadIdx.x;
    if (i < n4) {
        float4 v = ((const float4*)x)[i];
        __half2* yp = (__half2*)y + i * 2;
        yp[0] = __floats2half2_rn(v.x, v.y);
        yp[1] = __floats2half2_rn(v.z, v.w);
    }
}

__global__ void f2h4_kernel(const float* __restrict__ x0, const float* __restrict__ x1,
                            const float* __restrict__ x2, const float* __restrict__ x3,
                            __half* __restrict__ y0, __half* __restrict__ y1,
                            __half* __restrict__ y2, __half* __restrict__ y3, int n4)
{
    const float* x; __half* y;
    switch (blockIdx.y) {
        case 0:  x = x0; y = y0; break;
        case 1:  x = x1; y = y1; break;
        case 2:  x = x2; y = y2; break;
        default: x = x3; y = y3; break;
    }
    int i = blockIdx.x * blockDim.x + threadIdx.x;
    if (i < n4) {
        float4 v = ((const float4*)x)[i];
        __half2* yp = (__half2*)y + i * 2;
        yp[0] = __floats2half2_rn(v.x, v.y);
        yp[1] = __floats2half2_rn(v.z, v.w);
    }
}

// ================= fp16 HGEMM: Y[M,N] = A[M,K] @ B[N,K]^T + bias ====================
// CTA 128x128, BK=64, 2-stage double buffer, 256 threads (8 warps 4x2), warp 32x64.
// 24 barriers/CTA (vs 48 @BK=32); 64 MMA per warp between barriers.
#define LDA    72                       // halfs per smem row (144B, LDSM conflict-free)
#define ASTG   (128 * LDA)              // halfs per matrix buffer
#define STG2   (2 * ASTG)               // halfs per stage (A + B)
#define NSTAGE 2
#define GEMM_SMEM_BYTES (NSTAGE * STG2 * 2)   // 73728

template<bool HOUT>
__global__ __launch_bounds__(256, 2)
void hgemm_bias(const __half* __restrict__ A, const __half* __restrict__ B,
                const float* __restrict__ bias, void* __restrict__ Yv,
                const __half* __restrict__ B2, const float* __restrict__ bias2,
                void* __restrict__ Yv2, int nx1,
                int M, int N, int K)
{
    extern __shared__ __half sm[];
    const uint32_t sbase = smem_u32(sm);
    const int tid  = threadIdx.x;
    const int wid  = tid >> 5;
    const int lane = tid & 31;

    const __half* Bp = B;
    const float*  bp = bias;
    void*         Yp = Yv;
    int bx = blockIdx.x;
    if (B2 != nullptr && bx >= nx1) { Bp = B2; bp = bias2; Yp = Yv2; bx -= nx1; }

    const int bm   = blockIdx.y * 128;
    const int bn   = bx * 128;
    const int wm   = wid & 3;
    const int wn   = wid >> 2;
    const int xrow = lane & 15;
    const int xk   = (lane >> 4) << 3;

    // loader: per stage each thread moves 4 A-chunks + 4 B-chunks of 16B
    const int crow = tid >> 3;              // 0..31 (x4 strides of 32 -> 128 rows)
    const int ccol = (tid & 7) << 3;        // half col 0..56
    const __half* aptr[4];
    const __half* bptr[4];
    uint32_t soff[4];
    #pragma unroll
    for (int t = 0; t < 4; ++t) {
        int row = crow + t * 32;
        aptr[t] = A  + (size_t)min(bm + row, M - 1) * K + ccol;
        bptr[t] = Bp + (size_t)(bn + row) * K + ccol;
        soff[t] = (uint32_t)(row * LDA + ccol) * 2;
    }

    float acc[2][8][4];
    #pragma unroll
    for (int i = 0; i < 2; ++i)
        #pragma unroll
        for (int j = 0; j < 8; ++j)
            #pragma unroll
            for (int q = 0; q < 4; ++q) acc[i][j][q] = 0.f;

    const int NIT = K / 64;   // 24

    auto issue = [&](int it) {
        const int s  = it & 1;
        const int k0 = it * 64;
        uint32_t sa = sbase + (uint32_t)s * STG2 * 2;
        uint32_t sb = sa + ASTG * 2;
        #pragma unroll
        for (int t = 0; t < 4; ++t) {
            cp_async16(sa + soff[t], aptr[t] + k0);
            cp_async16(sb + soff[t], bptr[t] + k0);
        }
    };

    issue(0); CP_COMMIT();

    for (int it = 0; it < NIT; ++it) {
        CP_WAIT(0);
        __syncthreads();                   // stage it&1 ready; all warps done with it-1
        if (it + 1 < NIT) { issue(it + 1); CP_COMMIT(); }

        const uint32_t sa = sbase + (uint32_t)(it & 1) * STG2 * 2;
        const uint32_t sb = sa + ASTG * 2;

        #pragma unroll
        for (int kk = 0; kk < 4; ++kk) {
            const int k0 = kk * 16;
            // hoist ALL fragment loads for this k16 before the MMA run
            uint32_t af[2][4];
            #pragma unroll
            for (int mf = 0; mf < 2; ++mf)
                ldm_x4(af[mf], sa + (uint32_t)((wm * 32 + mf * 16 + xrow) * LDA + k0 + xk) * 2);
            uint32_t bf[4][4];
            #pragma unroll
            for (int nf4 = 0; nf4 < 4; ++nf4)
                ldm_x4(bf[nf4], sb + (uint32_t)((wn * 64 + nf4 * 16 + xrow) * LDA + k0 + xk) * 2);
            // 32 HMMAs, accumulators all distinct within the run
            #pragma unroll
            for (int nf4 = 0; nf4 < 4; ++nf4) {
                #pragma unroll
                for (int mf = 0; mf < 2; ++mf) {
                    mma16816h(acc[mf][nf4 * 2],     af[mf], bf[nf4][0], bf[nf4][2]);
                    mma16816h(acc[mf][nf4 * 2 + 1], af[mf], bf[nf4][1], bf[nf4][3]);
                }
            }
        }
    }
    __syncthreads();

    const int g  = lane >> 2;
    const int t2 = (lane & 3) << 1;
    #pragma unroll
    for (int mf = 0; mf < 2; ++mf) {
        int r0 = bm + wm * 32 + mf * 16 + g;
        #pragma unroll
        for (int nf = 0; nf < 8; ++nf) {
            int col = bn + wn * 64 + nf * 8 + t2;
            float bv0 = bp[col], bv1 = bp[col + 1];
            float v00 = acc[mf][nf][0] + bv0, v01 = acc[mf][nf][1] + bv1;
            float v10 = acc[mf][nf][2] + bv0, v11 = acc[mf][nf][3] + bv1;
            if (HOUT) {
                __half* Y = (__half*)Yp;
                if (r0 < M)     *(__half2*)(Y + (size_t)r0 * N + col)       = __floats2half2_rn(v00, v01);
                if (r0 + 8 < M) *(__half2*)(Y + (size_t)(r0 + 8) * N + col) = __floats2half2_rn(v10, v11);
            } else {
                float* Y = (float*)Yp;
                if (r0 < M)     *(float2*)(Y + (size_t)r0 * N + col)       = make_float2(v00, v01);
                if (r0 + 8 < M) *(float2*)(Y + (size_t)(r0 + 8) * N + col) = make_float2(v10, v11);
            }
        }
    }
}

// ================= register-softmax HMMA attention (dedup, e3-baseline) ===========
#define QST 72
#define KST 72
#define KV_MAT   (4 * 32 * KST * 2)              // 18432 B
#define KV_STAGE (2 * KV_MAT)                    // 36864 B (K + V)
#define ATTN_SMEM_BYTES (4 * 64 * QST * 2 + 2 * KV_STAGE)   // 110592

#define SM_SCALE 0.1803368801f

__global__ __launch_bounds__(128, 2)
void attn_reg(const __half* __restrict__ Q, const __half* __restrict__ K,
              const __half* __restrict__ V, __half* __restrict__ O)
{
    extern __shared__ char smemc[];
    __half* qb = (__half*)smemc;                 // [4][64][QST]
    const uint32_t qbu = smem_u32(qb);
    const uint32_t kvu = qbu + 4 * 64 * QST * 2;

    const int tid  = threadIdx.x;
    const int wid  = tid >> 5;
    const int lane = tid & 31;
    const int b    = blockIdx.z;
    const int h    = blockIdx.y;
    const int s0   = blockIdx.x * 64;

    const int sbase = wid * 16;
    const int xrow  = lane & 15;
    const int xk    = (lane >> 4) << 3;
    const int g     = lane >> 2;
    const int q2    = (lane & 3) << 1;

    #pragma unroll
    for (int it = 0; it < 16; ++it) {
        int i  = tid + it * 128;
        int cc = i >> 9, r = i & 511, si = r >> 3, d8 = (r & 7) << 3;
        const __half* gp = Q + ((size_t)(cc * N_B + b) * S_LEN + s0 + si) * D_MODEL + h * DH + d8;
        *(uint4*)(qb + (cc * 64 + si) * QST + d8) = *(const uint4*)gp;
    }

    const int NCH = (T_LEN + 31) / 32;   // 5

    auto issue = [&](int ch) {
        const int t0 = ch * 32;
        const uint32_t st = kvu + (uint32_t)(ch & 1) * KV_STAGE;
        #pragma unroll
        for (int it = 0; it < 8; ++it) {
            int i  = tid + it * 128;
            int cc = i >> 8, r = i & 255, tj = r >> 3, d8 = (r & 7) << 3;
            int t = min(t0 + tj, T_LEN - 1);
            size_t go = ((size_t)(cc * N_B + b) * T_LEN + t) * D_MODEL + h * DH + d8;
            uint32_t so = (uint32_t)((cc * 32 + tj) * KST + d8) * 2;
            cp_async16(st + so, K + go);
            cp_async16(st + KV_MAT + so, V + go);
        }
    };

    issue(0); CP_COMMIT();
    issue(1); CP_COMMIT();

    float oacc[4][8][4];
    #pragma unroll
    for (int c = 0; c < 4; ++c)
        #pragma unroll
        for (int j = 0; j < 8; ++j)
            #pragma unroll
            for (int e = 0; e < 4; ++e) oacc[c][j][e] = 0.f;
    float rsum[2][4];
    #pragma unroll
    for (int r = 0; r < 2; ++r)
        #pragma unroll
        for (int c = 0; c < 4; ++c) rsum[r][c] = 0.f;

    for (int ch = 0; ch < NCH; ++ch) {
        if (ch == NCH - 1) { CP_WAIT(0); } else { CP_WAIT(1); }
        __syncthreads();

        const uint32_t kbu = kvu + (uint32_t)(ch & 1) * KV_STAGE;
        const uint32_t vbu = kbu + KV_MAT;

        float sacc[4][4][4];
        #pragma unroll
        for (int c = 0; c < 4; ++c)
            #pragma unroll
            for (int j = 0; j < 4; ++j)
                #pragma unroll
                for (int e = 0; e < 4; ++e) sacc[c][j][e] = 0.f;

        #pragma unroll
        for (int c = 0; c < 4; ++c) {
            #pragma unroll
            for (int kk = 0; kk < 4; ++kk) {
                uint32_t af[4];
                ldm_x4(af, qbu + (uint32_t)((c * 64 + sbase + xrow) * QST + kk * 16 + xk) * 2);
                #pragma unroll
                for (int nf16 = 0; nf16 < 2; ++nf16) {
                    uint32_t bf[4];
                    ldm_x4(bf, kbu + (uint32_t)((c * 32 + nf16 * 16 + xrow) * KST + kk * 16 + xk) * 2);
                    mma16816h(sacc[c][nf16 * 2],     af, bf[0], bf[2]);
                    mma16816h(sacc[c][nf16 * 2 + 1], af, bf[1], bf[3]);
                }
            }
        }

        #pragma unroll
        for (int kk = 0; kk < 2; ++kk) {
            uint32_t wf[4][4];
            #pragma unroll
            for (int jh = 0; jh < 2; ++jh) {
                const int j = kk * 2 + jh;
                float wt[4][4];
                #pragma unroll
                for (int e = 0; e < 4; ++e) {
                    int col = ch * 32 + j * 8 + q2 + (e & 1);
                    float t3 = sacc[3][j][e] * SM_SCALE;
                    float e0 = ex2a(fmaf(sacc[0][j][e], SM_SCALE, -t3));
                    float e1 = ex2a(fmaf(sacc[1][j][e], SM_SCALE, -t3));
                    float e2 = ex2a(fmaf(sacc[2][j][e], SM_SCALE, -t3));
                    float inv = (col < T_LEN) ? rcpa(e0 + e1 + e2 + 1.f) : 0.f;
                    e0 *= inv; e1 *= inv; e2 *= inv;
                    int rr = e >> 1;
                    rsum[rr][0] += e0; rsum[rr][1] += e1;
                    rsum[rr][2] += e2; rsum[rr][3] += inv;
                    wt[0][e] = e0; wt[1][e] = e1; wt[2][e] = e2; wt[3][e] = inv;
                }
                #pragma unroll
                for (int c = 0; c < 4; ++c) {
                    wf[c][jh * 2 + 0] = packh2(wt[c][0], wt[c][1]);
                    wf[c][jh * 2 + 1] = packh2(wt[c][2], wt[c][3]);
                }
            }
            #pragma unroll
            for (int c = 0; c < 4; ++c) {
                #pragma unroll
                for (int nf16 = 0; nf16 < 4; ++nf16) {
                    uint32_t bf[4];
                    ldm_x4_t(bf, vbu + (uint32_t)((c * 32 + kk * 16 + xrow) * KST + nf16 * 16 + xk) * 2);
                    mma16816h(oacc[c][nf16 * 2],     wf[c], bf[0], bf[1]);
                    mma16816h(oacc[c][nf16 * 2 + 1], wf[c], bf[2], bf[3]);
                }
            }
        }
        __syncthreads();
        if (ch + 2 < NCH) { issue(ch + 2); CP_COMMIT(); }
    }

    #pragma unroll
    for (int x = 1; x <= 2; x <<= 1)
        #pragma unroll
        for (int r = 0; r < 2; ++r)
            #pragma unroll
            for (int c = 0; c < 4; ++c)
                rsum[r][c] += __shfl_xor_sync(0xffffffffu, rsum[r][c], x);

    #pragma unroll
    for (int c = 0; c < 4; ++c) {
        float inv0 = 1.f / (rsum[0][c] + 1e-8f);
        float inv1 = 1.f / (rsum[1][c] + 1e-8f);
        int row0 = s0 + sbase + g;
        __half* gp0 = O + ((size_t)(c * N_B + b) * S_LEN + row0) * D_MODEL + h * DH + q2;
        __half* gp1 = gp0 + (size_t)8 * D_MODEL;
        #pragma unroll
        for (int j = 0; j < 8; ++j) {
            *(__half2*)(gp0 + j * 8) = __floats2half2_rn(oacc[c][j][0] * inv0, oacc[c][j][1] * inv0);
            *(__half2*)(gp1 + j * 8) = __floats2half2_rn(oacc[c][j][2] * inv1, oacc[c][j][3] * inv1);
        }
    }
}

// ---------------- launch ----------------
extern "C" void kernel_launch(void* const* d_in, const int* in_sizes, int n_in,
                              void* d_out, int out_size)
{
    const float* HS  = (const float*)d_in[0];
    const float* EHS = (const float*)d_in[1];
    const float* Wq  = (const float*)d_in[2];
    const float* bq  = (const float*)d_in[3];
    const float* Wk  = (const float*)d_in[4];
    const float* bk  = (const float*)d_in[5];
    const float* Wv  = (const float*)d_in[6];
    const float* bv  = (const float*)d_in[7];
    const float* Wo  = (const float*)d_in[8];
    const float* bo  = (const float*)d_in[9];
    float* out = (float*)d_out;

    __half *pHSh, *pEHSh, *pQh, *pKh, *pVh, *pAOh, *pWqh, *pWkh, *pWvh, *pWoh;
    cudaGetSymbolAddress((void**)&pHSh,  g_HSh);
    cudaGetSymbolAddress((void**)&pEHSh, g_EHSh);
    cudaGetSymbolAddress((void**)&pQh,   g_Qh);
    cudaGetSymbolAddress((void**)&pKh,   g_Kh);
    cudaGetSymbolAddress((void**)&pVh,   g_Vh);
    cudaGetSymbolAddress((void**)&pAOh,  g_AOh);
    cudaGetSymbolAddress((void**)&pWqh,  g_Wqh);
    cudaGetSymbolAddress((void**)&pWkh,  g_Wkh);
    cudaGetSymbolAddress((void**)&pWvh,  g_Wvh);
    cudaGetSymbolAddress((void**)&pWoh,  g_Woh);

    cudaFuncSetAttribute(hgemm_bias<true>,  cudaFuncAttributeMaxDynamicSharedMemorySize, GEMM_SMEM_BYTES);
    cudaFuncSetAttribute(hgemm_bias<false>, cudaFuncAttributeMaxDynamicSharedMemorySize, GEMM_SMEM_BYTES);
    cudaFuncSetAttribute(attn_reg, cudaFuncAttributeMaxDynamicSharedMemorySize, ATTN_SMEM_BYTES);

    const int nHS = N_BC * S_LEN * D_MODEL / 4;
    const int nEH = N_BC * T_LEN * D_MODEL / 4;
    const int nW  = D_MODEL * D_MODEL / 4;
    f2h_kernel<<<(nHS + 255) / 256, 256>>>(HS,  pHSh,  nHS);
    f2h_kernel<<<(nEH + 255) / 256, 256>>>(EHS, pEHSh, nEH);
    f2h4_kernel<<<dim3((nW + 255) / 256, 4), 256>>>(Wq, Wk, Wv, Wo,
                                                    pWqh, pWkh, pWvh, pWoh, nW);

    dim3 gblk(256);
    // Q projection (fp16 out)
    hgemm_bias<true><<<dim3(12, 256), gblk, GEMM_SMEM_BYTES>>>(
        pHSh, pWqh, bq, pQh, nullptr, nullptr, nullptr, 0,
        N_BC * S_LEN, D_MODEL, D_MODEL);
    // merged K + V projections (fp16 out)
    hgemm_bias<true><<<dim3(24, 10), gblk, GEMM_SMEM_BYTES>>>(
        pEHSh, pWkh, bk, pKh, pWvh, bv, pVh, 12,
        N_BC * T_LEN, D_MODEL, D_MODEL);
    // dedup register-softmax HMMA attention (s-tile 64)
    attn_reg<<<dim3(S_LEN / 64, N_H, N_B), 128, ATTN_SMEM_BYTES>>>(pQh, pKh, pVh, pAOh);
    // output projection (fp32 output into d_out)
    hgemm_bias<false><<<dim3(12, 256), gblk, GEMM_SMEM_BYTES>>>(
        pAOh, pWoh, bo, out, nullptr, nullptr, nullptr, 0,
        N_BC * S_LEN, D_MODEL, D_MODEL);
}